// round 13
// baseline (speedup 1.0000x reference)
#include <cuda_runtime.h>
#include <cuda_fp16.h>
#include <cuda_bf16.h>
#include <cstdint>

// ---------------- problem constants ----------------
#define BATCH  256
#define NPIX   49152
#define NRET   3072
#define NLGN   3072
#define NV1    6144
#define NIT    3072
#define NCLS   1000
#define NCLSP  1024
#define NK     NIT

#define MAX1   128
#define MAX2   256
#define KSPLIT 8

// phase-1 block roles
#define RET_BX   96
#define RET_BY   8
#define RET_BLKS (RET_BX * RET_BY)       // 768
#define CSR1_BLKS (NV1 / 8)              // 768
#define CSR2_BLKS (NIT / 8)              // 384
#define SUMS_BLKS ((NRET + NV1 + NIT + 255) / 256)  // 48
#define WPREP_BLKS (NCLSP / 4)           // 256

// ---------------- device scratch ----------------
__device__ __half2       g_r2t2[NRET * BATCH / 2];
__device__ __half2       g_r3t2[NV1 * BATCH / 2];
__device__ float         g_r4t[NIT * BATCH];          // [k, b] fp32
__device__ float         g_sums[NRET + NV1 + NIT];
__device__ int           g_idx1[NV1 * MAX1];
__device__ int           g_cnt1[NV1];
__device__ int           g_idx2[NIT * MAX2];
__device__ int           g_cnt2[NIT];
__device__ float         g_part[KSPLIT * NCLSP * BATCH];
__device__ __nv_bfloat16 g_whi[NCLSP * NK];           // W hi, [c, k]
__device__ __nv_bfloat16 g_wlo[NCLSP * NK];           // W lo
__device__ unsigned      g_tile_cnt[(NCLSP / 128) * (BATCH / 64)]; // 32, zero-init

__device__ __forceinline__ float sigmoidf_(float z) {
    return 1.0f / (1.0f + __expf(-z));
}

// ---------------- warp MMA: m16n8k16 bf16 ----------------
__device__ __forceinline__ void mma16816(float* c, const uint32_t* a,
                                         const uint32_t* b) {
    asm volatile(
        "mma.sync.aligned.m16n8k16.row.col.f32.bf16.bf16.f32 "
        "{%0,%1,%2,%3}, {%4,%5,%6,%7}, {%8,%9}, {%0,%1,%2,%3};"
        : "+f"(c[0]), "+f"(c[1]), "+f"(c[2]), "+f"(c[3])
        : "r"(a[0]), "r"(a[1]), "r"(a[2]), "r"(a[3]),
          "r"(b[0]), "r"(b[1]));
}

__device__ __forceinline__ uint32_t pack_bf2(__nv_bfloat16 lo, __nv_bfloat16 hi) {
    __nv_bfloat162 v = __halves2bfloat162(lo, hi);  // .x = low half-word
    return *(uint32_t*)&v;
}

// ---------------- phase-1 role: CSR build ----------------
__device__ __forceinline__ void csr_row(const int* __restrict__ m, int cols,
                                        int maxnnz, int* __restrict__ idx,
                                        int* __restrict__ cnt, int row, int lane) {
    const int4* row4 = (const int4*)(m + (long long)row * cols);
    int* out = idx + (long long)row * maxnnz;
    unsigned lt = (1u << lane) - 1;
    int c = 0;
    int iters = cols >> 7;
    for (int it = 0; it < iters; it++) {
        int4 v = row4[it * 32 + lane];
        int cbase = it * 128 + 4 * lane;
        #pragma unroll
        for (int e = 0; e < 4; e++) {
            int val = (e == 0) ? v.x : (e == 1) ? v.y : (e == 2) ? v.z : v.w;
            unsigned msk = __ballot_sync(0xffffffffu, val != 0);
            if (val) {
                int pos = c + __popc(msk & lt);
                if (pos < maxnnz) out[pos] = cbase + e;
            }
            c += __popc(msk);
        }
    }
    if (lane == 0) cnt[row] = (c < maxnnz) ? c : maxnnz;
}

// ---------------- phase-1 mega-kernel ----------------
__global__ void phase1_kernel(const float* __restrict__ x,
                              const int* __restrict__ pm,
                              const float* __restrict__ w_ret,
                              const float* __restrict__ b_ret,
                              const float* __restrict__ w_lgn,
                              const float* __restrict__ b_lgn,
                              const float* __restrict__ w_v1,
                              const float* __restrict__ w_it,
                              const float* __restrict__ W_cls,
                              const int* __restrict__ m1,
                              const int* __restrict__ m2,
                              __half* __restrict__ r2t,
                              float* __restrict__ sums,
                              int* __restrict__ idx1, int* __restrict__ cnt1,
                              int* __restrict__ idx2, int* __restrict__ cnt2,
                              __nv_bfloat16* __restrict__ whi,
                              __nv_bfloat16* __restrict__ wlo) {
    int blk = blockIdx.x;
    int t = threadIdx.x;
    int lane = t & 31;
    int w = t >> 5;

    if (blk < RET_BLKS) {
        __shared__ float s[32][33];
        int bn = blk % RET_BX;
        int bb = blk / RET_BX;
        int n = bn * 32 + lane;
        int b0 = bb * 32 + w * 4;
        int base = n * 16;

        const int4*   pm4 = (const int4*)(pm + base);
        const float4* w4  = (const float4*)(w_ret + base);
        float4 ww[4];
        int4 pp[4];
        bool fast = true;
        #pragma unroll
        for (int q = 0; q < 4; q++) {
            pp[q] = pm4[q];
            ww[q] = w4[q];
            int e = base + 4 * q;
            fast = fast && (pp[q].x == e) && (pp[q].y == e + 1) &&
                   (pp[q].z == e + 2) && (pp[q].w == e + 3);
        }
        float acc[4] = {0.f, 0.f, 0.f, 0.f};
        if (fast) {
            #pragma unroll
            for (int p = 0; p < 4; p++) {
                const float4* xp = (const float4*)(x + (long long)(b0 + p) * NPIX + base);
                #pragma unroll
                for (int q = 0; q < 4; q++) {
                    float4 xv = xp[q];
                    acc[p] += xv.x * ww[q].x + xv.y * ww[q].y +
                              xv.z * ww[q].z + xv.w * ww[q].w;
                }
            }
        } else {
            #pragma unroll
            for (int p = 0; p < 4; p++) {
                const float* xb = x + (long long)(b0 + p) * NPIX;
                #pragma unroll
                for (int q = 0; q < 4; q++) {
                    acc[p] += xb[pp[q].x] * ww[q].x + xb[pp[q].y] * ww[q].y +
                              xb[pp[q].z] * ww[q].z + xb[pp[q].w] * ww[q].w;
                }
            }
        }
        float br = b_ret[n];
        float sl = 0.f;
        {
            const float4* wl = (const float4*)(w_lgn + base);
            #pragma unroll
            for (int q = 0; q < 4; q++) {
                float4 v = wl[q];
                sl += v.x + v.y + v.z + v.w;
            }
        }
        float bl = b_lgn[n];
        #pragma unroll
        for (int p = 0; p < 4; p++) {
            float r1 = sigmoidf_(acc[p] - br);
            s[lane][w * 4 + p] = sigmoidf_(r1 * sl - bl);
        }
        __syncthreads();
        #pragma unroll
        for (int i = 0; i < 4; i++) {
            int id = t + i * 256;
            int n_o = id >> 5, b_o = id & 31;
            r2t[(long long)(bn * 32 + n_o) * BATCH + bb * 32 + b_o] =
                __float2half(s[n_o][b_o]);
        }
        return;
    }
    blk -= RET_BLKS;
    if (blk < CSR1_BLKS) {
        csr_row(m1, NLGN, MAX1, idx1, cnt1, blk * 8 + w, lane);
        return;
    }
    blk -= CSR1_BLKS;
    if (blk < CSR2_BLKS) {
        csr_row(m2, NV1, MAX2, idx2, cnt2, blk * 8 + w, lane);
        return;
    }
    blk -= CSR2_BLKS;
    if (blk < SUMS_BLKS) {
        int i = blk * 256 + t;
        if (i < NRET) {
            float s2 = 0.f;
            #pragma unroll
            for (int k = 0; k < 16; k++) s2 += w_lgn[i * 16 + k];
            sums[i] = s2;
        } else if (i < NRET + NV1) {
            int j = i - NRET;
            float s2 = 0.f;
            #pragma unroll
            for (int k = 0; k < 32; k++) s2 += w_v1[j * 32 + k];
            sums[NRET + j] = s2;
        } else if (i < NRET + NV1 + NIT) {
            int j = i - NRET - NV1;
            float s2 = 0.f;
            #pragma unroll
            for (int k = 0; k < 32; k++) s2 += w_it[j * 32 + k];
            sums[NRET + NV1 + j] = s2;
        }
        return;
    }
    blk -= SUMS_BLKS;
    {
        int row0 = blk * 4;
        #pragma unroll
        for (int rr = 0; rr < 4; rr++) {
            int r = row0 + rr;
            long long rb = (long long)r * NK;
            #pragma unroll
            for (int i = 0; i < NK / 256; i++) {
                int col = i * 256 + t;
                float v = (r < NCLS) ? W_cls[rb + col] : 0.f;
                __nv_bfloat16 hi = __float2bfloat16(v);
                __nv_bfloat16 lo = __float2bfloat16(v - __bfloat162float(hi));
                whi[rb + col] = hi;
                wlo[rb + col] = lo;
            }
        }
    }
}

// ---------------- SpMM kernels ----------------
__global__ void spmm_act_h2h(const int* __restrict__ idx,
                             const int* __restrict__ cnt, int maxnnz,
                             const __half2* __restrict__ src2,
                             const float* __restrict__ s,
                             const float* __restrict__ bias,
                             __half2* __restrict__ dst2) {
    int j = blockIdx.x * 2 + (threadIdx.x >> 7);
    int b2 = threadIdx.x & 127;
    int n = cnt[j];
    const int* ji = idx + (long long)j * maxnnz;
    float ax = 0.f, ay = 0.f, cx = 0.f, cy = 0.f;
    int k = 0;
    for (; k + 8 <= n; k += 8) {
        float2 v0 = __half22float2(src2[ji[k+0] * (BATCH/2) + b2]);
        float2 v1 = __half22float2(src2[ji[k+1] * (BATCH/2) + b2]);
        float2 v2 = __half22float2(src2[ji[k+2] * (BATCH/2) + b2]);
        float2 v3 = __half22float2(src2[ji[k+3] * (BATCH/2) + b2]);
        float2 v4 = __half22float2(src2[ji[k+4] * (BATCH/2) + b2]);
        float2 v5 = __half22float2(src2[ji[k+5] * (BATCH/2) + b2]);
        float2 v6 = __half22float2(src2[ji[k+6] * (BATCH/2) + b2]);
        float2 v7 = __half22float2(src2[ji[k+7] * (BATCH/2) + b2]);
        ax += (v0.x + v1.x) + (v2.x + v3.x);
        ay += (v0.y + v1.y) + (v2.y + v3.y);
        cx += (v4.x + v5.x) + (v6.x + v7.x);
        cy += (v4.y + v5.y) + (v6.y + v7.y);
    }
    for (; k < n; k++) {
        float2 v = __half22float2(src2[ji[k] * (BATCH/2) + b2]);
        ax += v.x; ay += v.y;
    }
    ax += cx; ay += cy;
    float sj = s[j], bj = bias[j], fn = (float)n;
    float ox = sigmoidf_((ax / fn) * sj - bj);
    float oy = sigmoidf_((ay / fn) * sj - bj);
    dst2[(long long)j * (BATCH/2) + b2] = __floats2half2_rn(ox, oy);
}

__global__ void spmm_act_h2f(const int* __restrict__ idx,
                             const int* __restrict__ cnt, int maxnnz,
                             const __half2* __restrict__ src2,
                             const float* __restrict__ s,
                             const float* __restrict__ bias,
                             float* __restrict__ dst) {
    int j = blockIdx.x * 2 + (threadIdx.x >> 7);
    int b2 = threadIdx.x & 127;
    int n = cnt[j];
    const int* ji = idx + (long long)j * maxnnz;
    float ax = 0.f, ay = 0.f, cx = 0.f, cy = 0.f;
    int k = 0;
    for (; k + 8 <= n; k += 8) {
        float2 v0 = __half22float2(src2[ji[k+0] * (BATCH/2) + b2]);
        float2 v1 = __half22float2(src2[ji[k+1] * (BATCH/2) + b2]);
        float2 v2 = __half22float2(src2[ji[k+2] * (BATCH/2) + b2]);
        float2 v3 = __half22float2(src2[ji[k+3] * (BATCH/2) + b2]);
        float2 v4 = __half22float2(src2[ji[k+4] * (BATCH/2) + b2]);
        float2 v5 = __half22float2(src2[ji[k+5] * (BATCH/2) + b2]);
        float2 v6 = __half22float2(src2[ji[k+6] * (BATCH/2) + b2]);
        float2 v7 = __half22float2(src2[ji[k+7] * (BATCH/2) + b2]);
        ax += (v0.x + v1.x) + (v2.x + v3.x);
        ay += (v0.y + v1.y) + (v2.y + v3.y);
        cx += (v4.x + v5.x) + (v6.x + v7.x);
        cy += (v4.y + v5.y) + (v6.y + v7.y);
    }
    for (; k < n; k++) {
        float2 v = __half22float2(src2[ji[k] * (BATCH/2) + b2]);
        ax += v.x; ay += v.y;
    }
    ax += cx; ay += cy;
    float sj = s[j], bj = bias[j], fn = (float)n;
    float2 o;
    o.x = sigmoidf_((ax / fn) * sj - bj);
    o.y = sigmoidf_((ay / fn) * sj - bj);
    *(float2*)(dst + (long long)j * BATCH + 2 * b2) = o;
}

// ---------------- classifier GEMM via mma.sync, fused A-prep + reduce ------
// CTA tile 128c x 64b, k-chunk 32, 8 warps, warp tile 32c x 32b, split-K 8.
// A consumed directly from r4t [k,b] fp32: transpose+bf16-split in smem.
#define KCH       (NK / KSPLIT / 32)     // 12
#define SROW      80
#define WHI_OFF   0
#define WLO_OFF   (128 * SROW)           // 10240
#define AHI_OFF   (2 * 128 * SROW)       // 20480
#define ALO_OFF   (AHI_OFF + 64 * SROW)  // 25600
#define STAGE2_B  (ALO_OFF + 64 * SROW)  // 30720
#define TROW      68                     // tbuf row, floats (272B, 16B-aligned)
#define TBUF_B    (32 * TROW * 4)        // 8704
#define TBUF_OFF  (2 * STAGE2_B)         // 61440
#define GEMM2_SMEM (TBUF_OFF + 2 * TBUF_B) // 78848

__global__ void __launch_bounds__(256, 2)
cls_gemm_mma(const __nv_bfloat16* __restrict__ whi,
             const __nv_bfloat16* __restrict__ wlo,
             const float* __restrict__ r4t,
             float* __restrict__ part,
             const float* __restrict__ b_cls,
             float* __restrict__ out,
             unsigned* __restrict__ tile_cnt) {
    extern __shared__ char sm[];
    __shared__ unsigned s_arrive;
    int t = threadIdx.x;
    int lane = t & 31, wid = t >> 5;
    int gid = lane >> 2, tig = lane & 3;
    int wm = wid & 3, wn = wid >> 2;
    int c0 = blockIdx.x * 128, b0 = blockIdx.y * 64, ks = blockIdx.z;
    int kbase = ks * (NK / KSPLIT);

    int r = t >> 2, q = t & 3;           // W loader role
    int akk = t >> 3, abq = t & 7;       // A loader role (32 k rows x 8 b-groups)
    float acc[2][4][4];
    #pragma unroll
    for (int i = 0; i < 2; i++)
        #pragma unroll
        for (int j = 0; j < 4; j++)
            #pragma unroll
            for (int e = 0; e < 4; e++) acc[i][j][e] = 0.f;

    int4 wg[4];
    float4 af[2];
    #define LOADW(K0) do {                                                    \
        long long wo0 = ((long long)(c0 + r) * NK + (K0)) * 2 + q * 16;       \
        long long wo1 = ((long long)(c0 + r + 64) * NK + (K0)) * 2 + q * 16;  \
        wg[0] = *(const int4*)((const char*)whi + wo0);                       \
        wg[1] = *(const int4*)((const char*)whi + wo1);                       \
        wg[2] = *(const int4*)((const char*)wlo + wo0);                       \
        wg[3] = *(const int4*)((const char*)wlo + wo1);                       \
    } while (0)
    #define LOADA(K0) do {                                                    \
        const float* ap = r4t + (long long)((K0) + akk) * BATCH + b0 + abq * 8; \
        af[0] = *(const float4*)ap;                                           \
        af[1] = *(const float4*)(ap + 4);                                     \
    } while (0)
    #define STOREW(BUF) do {                                                  \
        char* s_ = sm + (BUF) * STAGE2_B;                                     \
        *(int4*)(s_ + WHI_OFF + r * SROW + q * 16) = wg[0];                   \
        *(int4*)(s_ + WHI_OFF + (r + 64) * SROW + q * 16) = wg[1];            \
        *(int4*)(s_ + WLO_OFF + r * SROW + q * 16) = wg[2];                   \
        *(int4*)(s_ + WLO_OFF + (r + 64) * SROW + q * 16) = wg[3];            \
    } while (0)
    #define STOREAF(TB) do {                                                  \
        float* tb = (float*)(sm + TBUF_OFF + (TB) * TBUF_B);                  \
        *(float4*)(tb + akk * TROW + abq * 8) = af[0];                        \
        *(float4*)(tb + akk * TROW + abq * 8 + 4) = af[1];                    \
    } while (0)
    // transpose + hi/lo split: tbuf [32k][64b] f32 -> abf [64b][32k] bf16
    #define CVTSTOREA(TB, BUF) do {                                           \
        const float* tb = (const float*)(sm + TBUF_OFF + (TB) * TBUF_B);      \
        int b_loc = t & 63, kg = t >> 6;                                      \
        uint32_t hp[4], lp[4];                                                \
        _Pragma("unroll")                                                     \
        for (int i = 0; i < 4; i++) {                                         \
            float f0 = tb[(kg * 8 + 2 * i) * TROW + b_loc];                   \
            float f1 = tb[(kg * 8 + 2 * i + 1) * TROW + b_loc];               \
            __nv_bfloat16 h0 = __float2bfloat16(f0);                          \
            __nv_bfloat16 h1 = __float2bfloat16(f1);                          \
            __nv_bfloat16 l0 = __float2bfloat16(f0 - __bfloat162float(h0));   \
            __nv_bfloat16 l1 = __float2bfloat16(f1 - __bfloat162float(h1));   \
            hp[i] = pack_bf2(h0, h1);                                         \
            lp[i] = pack_bf2(l0, l1);                                         \
        }                                                                     \
        char* s_ = sm + (BUF) * STAGE2_B;                                     \
        *(uint4*)(s_ + AHI_OFF + b_loc * SROW + kg * 16) =                    \
            make_uint4(hp[0], hp[1], hp[2], hp[3]);                           \
        *(uint4*)(s_ + ALO_OFF + b_loc * SROW + kg * 16) =                    \
            make_uint4(lp[0], lp[1], lp[2], lp[3]);                           \
    } while (0)

    LOADW(kbase); LOADA(kbase);
    STOREW(0); STOREAF(0);
    __syncthreads();

    for (int j = 0; j < KCH; j++) {
        if (j + 1 < KCH) { LOADW(kbase + (j + 1) * 32); LOADA(kbase + (j + 1) * 32); }
        CVTSTOREA(j & 1, j & 1);
        __syncthreads();
        const char* s_ = sm + (j & 1) * STAGE2_B;
        #pragma unroll
        for (int s = 0; s < 2; s++) {
            int kb = s * 32 + tig * 4;
            uint32_t wa[2][4], wl[2][4];
            #pragma unroll
            for (int i = 0; i < 2; i++) {
                int cr = wm * 32 + i * 16 + gid;
                const char* wr = s_ + WHI_OFF + cr * SROW;
                wa[i][0] = *(const uint32_t*)(wr + kb);
                wa[i][1] = *(const uint32_t*)(wr + 8 * SROW + kb);
                wa[i][2] = *(const uint32_t*)(wr + kb + 16);
                wa[i][3] = *(const uint32_t*)(wr + 8 * SROW + kb + 16);
                const char* lr = s_ + WLO_OFF + cr * SROW;
                wl[i][0] = *(const uint32_t*)(lr + kb);
                wl[i][1] = *(const uint32_t*)(lr + 8 * SROW + kb);
                wl[i][2] = *(const uint32_t*)(lr + kb + 16);
                wl[i][3] = *(const uint32_t*)(lr + 8 * SROW + kb + 16);
            }
            #pragma unroll
            for (int jj = 0; jj < 4; jj++) {
                int br = wn * 32 + jj * 8 + gid;
                const char* ar = s_ + AHI_OFF + br * SROW;
                const char* orow = s_ + ALO_OFF + br * SROW;
                uint32_t bh[2], bl[2];
                bh[0] = *(const uint32_t*)(ar + kb);
                bh[1] = *(const uint32_t*)(ar + kb + 16);
                bl[0] = *(const uint32_t*)(orow + kb);
                bl[1] = *(const uint32_t*)(orow + kb + 16);
                mma16816(acc[0][jj], wa[0], bh);
                mma16816(acc[1][jj], wa[1], bh);
                mma16816(acc[0][jj], wa[0], bl);
                mma16816(acc[1][jj], wa[1], bl);
                mma16816(acc[0][jj], wl[0], bh);
                mma16816(acc[1][jj], wl[1], bh);
            }
        }
        if (j + 1 < KCH) { STOREW((j + 1) & 1); STOREAF((j + 1) & 1); }
        __syncthreads();
    }

    // store partials
    #pragma unroll
    for (int i = 0; i < 2; i++) {
        int c = c0 + wm * 32 + i * 16 + gid;
        #pragma unroll
        for (int jj = 0; jj < 4; jj++) {
            int b = b0 + wn * 32 + jj * 8 + 2 * tig;
            float2 lo = make_float2(acc[i][jj][0], acc[i][jj][1]);
            float2 hi = make_float2(acc[i][jj][2], acc[i][jj][3]);
            *(float2*)(part + ((long long)ks * NCLSP + c) * BATCH + b) = lo;
            *(float2*)(part + ((long long)ks * NCLSP + c + 8) * BATCH + b) = hi;
        }
    }
    // fused split-K reduce: 8th-arriving CTA per (c-tile, b-tile) reduces
    __threadfence();
    __syncthreads();
    if (t == 0)
        s_arrive = atomicAdd(&tile_cnt[blockIdx.x * (BATCH / 64) + blockIdx.y], 1u);
    __syncthreads();
    if (s_arrive == KSPLIT - 1) {
        __threadfence();
        for (int u = t; u < 128 * 64; u += 256) {
            int c = c0 + (u >> 6);
            int b = b0 + (u & 63);
            if (c < NCLS) {
                float acc2 = b_cls[c];
                #pragma unroll
                for (int kk = 0; kk < KSPLIT; kk++)
                    acc2 += part[((long long)kk * NCLSP + c) * BATCH + b];
                out[(long long)b * NCLS + c] = acc2;
            }
        }
        __syncthreads();
        if (t == 0)
            atomicExch(&tile_cnt[blockIdx.x * (BATCH / 64) + blockIdx.y], 0u);
    }
    #undef LOADW
    #undef LOADA
    #undef STOREW
    #undef STOREAF
    #undef CVTSTOREA
}

// ---------------- launch ----------------
extern "C" void kernel_launch(void* const* d_in, const int* in_sizes, int n_in,
                              void* d_out, int out_size) {
    const float* x        = (const float*)d_in[0];
    const float* w_ret    = (const float*)d_in[1];
    const float* b_ret    = (const float*)d_in[2];
    const float* w_lgn    = (const float*)d_in[3];
    const float* b_lgn    = (const float*)d_in[4];
    const float* w_v1     = (const float*)d_in[5];
    const float* b_v1     = (const float*)d_in[6];
    const float* w_it     = (const float*)d_in[7];
    const float* b_it     = (const float*)d_in[8];
    const float* W_cls    = (const float*)d_in[9];
    const float* b_cls    = (const float*)d_in[10];
    const int*   pixel_map= (const int*)d_in[11];
    const int*   m1       = (const int*)d_in[12];
    const int*   m2       = (const int*)d_in[13];
    float* out = (float*)d_out;

    __half2* r2t2 = nullptr; __half2* r3t2 = nullptr; float* r4t = nullptr;
    float* sums = nullptr; float* partp = nullptr;
    int *idx1 = nullptr, *cnt1 = nullptr, *idx2 = nullptr, *cnt2 = nullptr;
    __nv_bfloat16 *whi = nullptr, *wlo = nullptr;
    unsigned* tcnt = nullptr;
    cudaGetSymbolAddress((void**)&r2t2, g_r2t2);
    cudaGetSymbolAddress((void**)&r3t2, g_r3t2);
    cudaGetSymbolAddress((void**)&r4t,  g_r4t);
    cudaGetSymbolAddress((void**)&sums, g_sums);
    cudaGetSymbolAddress((void**)&partp,g_part);
    cudaGetSymbolAddress((void**)&idx1, g_idx1);
    cudaGetSymbolAddress((void**)&cnt1, g_cnt1);
    cudaGetSymbolAddress((void**)&idx2, g_idx2);
    cudaGetSymbolAddress((void**)&cnt2, g_cnt2);
    cudaGetSymbolAddress((void**)&whi,  g_whi);
    cudaGetSymbolAddress((void**)&wlo,  g_wlo);
    cudaGetSymbolAddress((void**)&tcnt, g_tile_cnt);

    cudaFuncSetAttribute(cls_gemm_mma,
                         cudaFuncAttributeMaxDynamicSharedMemorySize, GEMM2_SMEM);

    // phase 1: retina+LGN, CSR builds, weight sums, W bf16 split
    {
        int nblk = RET_BLKS + CSR1_BLKS + CSR2_BLKS + SUMS_BLKS + WPREP_BLKS;
        phase1_kernel<<<nblk, 256>>>(x, pixel_map, w_ret, b_ret, w_lgn, b_lgn,
                                     w_v1, w_it, W_cls, m1, m2, (__half*)r2t2,
                                     sums, idx1, cnt1, idx2, cnt2, whi, wlo);
    }
    // V1
    spmm_act_h2h<<<NV1 / 2, 256>>>(idx1, cnt1, MAX1, r2t2,
                                   sums + NRET, b_v1, r3t2);
    // IT
    spmm_act_h2f<<<NIT / 2, 256>>>(idx2, cnt2, MAX2, r3t2,
                                   sums + NRET + NV1, b_it, r4t);
    // classifier (fused A-prep + split-K GEMM + reduce + bias)
    {
        dim3 grid(NCLSP / 128, BATCH / 64, KSPLIT);
        cls_gemm_mma<<<grid, 256, GEMM2_SMEM>>>(whi, wlo, r4t, partp,
                                                b_cls, out, tcnt);
    }
    (void)in_sizes; (void)n_in; (void)out_size;
}

// round 14
// speedup vs baseline: 1.0872x; 1.0872x over previous
#include <cuda_runtime.h>
#include <cuda_fp16.h>
#include <cuda_bf16.h>
#include <cstdint>

// ---------------- problem constants ----------------
#define BATCH  256
#define NPIX   49152
#define NRET   3072
#define NLGN   3072
#define NV1    6144
#define NIT    3072
#define NCLS   1000
#define NCLSP  1024
#define NK     NIT

#define MAX1   128
#define MAX2   256
#define KSPLIT 8

// phase-1 block roles
#define RET_BX   96
#define RET_BY   8
#define RET_BLKS (RET_BX * RET_BY)       // 768
#define CSR1_BLKS (NV1 / 8)              // 768
#define CSR2_BLKS (NIT / 8)              // 384
#define SUMS_BLKS ((NRET + NV1 + NIT + 255) / 256)  // 48
#define WPREP_BLKS (NCLSP / 4)           // 256

// ---------------- device scratch ----------------
__device__ __half2       g_r2t2[NRET * BATCH / 2];
__device__ __half2       g_r3t2[NV1 * BATCH / 2];
__device__ float         g_r4t[NIT * BATCH];          // [k, b] fp32
__device__ float         g_sums[NRET + NV1 + NIT];
__device__ int           g_idx1[NV1 * MAX1];
__device__ int           g_cnt1[NV1];
__device__ int           g_idx2[NIT * MAX2];
__device__ int           g_cnt2[NIT];
__device__ float         g_part[KSPLIT * NCLSP * BATCH];
__device__ __nv_bfloat16 g_whi[NCLSP * NK];           // W hi, [c, k]
__device__ __nv_bfloat16 g_wlo[NCLSP * NK];           // W lo
__device__ __nv_bfloat16 g_ahi[BATCH * NK];           // acts hi, [b, k]
__device__ __nv_bfloat16 g_alo[BATCH * NK];           // acts lo

__device__ __forceinline__ float sigmoidf_(float z) {
    return 1.0f / (1.0f + __expf(-z));
}

// ---------------- warp MMA + ldmatrix ----------------
__device__ __forceinline__ void mma16816(float* c, const uint32_t* a,
                                         const uint32_t* b) {
    asm volatile(
        "mma.sync.aligned.m16n8k16.row.col.f32.bf16.bf16.f32 "
        "{%0,%1,%2,%3}, {%4,%5,%6,%7}, {%8,%9}, {%0,%1,%2,%3};"
        : "+f"(c[0]), "+f"(c[1]), "+f"(c[2]), "+f"(c[3])
        : "r"(a[0]), "r"(a[1]), "r"(a[2]), "r"(a[3]),
          "r"(b[0]), "r"(b[1]));
}
__device__ __forceinline__ void ldsm_x4(uint32_t* r, uint32_t addr) {
    asm volatile(
        "ldmatrix.sync.aligned.m8n8.x4.shared.b16 {%0,%1,%2,%3}, [%4];"
        : "=r"(r[0]), "=r"(r[1]), "=r"(r[2]), "=r"(r[3]) : "r"(addr));
}
__device__ __forceinline__ uint32_t smem_u32(const void* p) {
    uint32_t a;
    asm("{ .reg .u64 t; cvta.to.shared.u64 t, %1; cvt.u32.u64 %0, t; }"
        : "=r"(a) : "l"(p));
    return a;
}

// ---------------- phase-1 role: CSR build ----------------
__device__ __forceinline__ void csr_row(const int* __restrict__ m, int cols,
                                        int maxnnz, int* __restrict__ idx,
                                        int* __restrict__ cnt, int row, int lane) {
    const int4* row4 = (const int4*)(m + (long long)row * cols);
    int* out = idx + (long long)row * maxnnz;
    unsigned lt = (1u << lane) - 1;
    int c = 0;
    int iters = cols >> 7;
    for (int it = 0; it < iters; it++) {
        int4 v = row4[it * 32 + lane];
        int cbase = it * 128 + 4 * lane;
        #pragma unroll
        for (int e = 0; e < 4; e++) {
            int val = (e == 0) ? v.x : (e == 1) ? v.y : (e == 2) ? v.z : v.w;
            unsigned msk = __ballot_sync(0xffffffffu, val != 0);
            if (val) {
                int pos = c + __popc(msk & lt);
                if (pos < maxnnz) out[pos] = cbase + e;
            }
            c += __popc(msk);
        }
    }
    if (lane == 0) cnt[row] = (c < maxnnz) ? c : maxnnz;
}

// ---------------- phase-1 mega-kernel ----------------
__global__ void phase1_kernel(const float* __restrict__ x,
                              const int* __restrict__ pm,
                              const float* __restrict__ w_ret,
                              const float* __restrict__ b_ret,
                              const float* __restrict__ w_lgn,
                              const float* __restrict__ b_lgn,
                              const float* __restrict__ w_v1,
                              const float* __restrict__ w_it,
                              const float* __restrict__ W_cls,
                              const int* __restrict__ m1,
                              const int* __restrict__ m2,
                              __half* __restrict__ r2t,
                              float* __restrict__ sums,
                              int* __restrict__ idx1, int* __restrict__ cnt1,
                              int* __restrict__ idx2, int* __restrict__ cnt2,
                              __nv_bfloat16* __restrict__ whi,
                              __nv_bfloat16* __restrict__ wlo) {
    int blk = blockIdx.x;
    int t = threadIdx.x;
    int lane = t & 31;
    int w = t >> 5;

    if (blk < RET_BLKS) {
        __shared__ float s[32][33];
        int bn = blk % RET_BX;
        int bb = blk / RET_BX;
        int n = bn * 32 + lane;
        int b0 = bb * 32 + w * 4;
        int base = n * 16;

        const int4*   pm4 = (const int4*)(pm + base);
        const float4* w4  = (const float4*)(w_ret + base);
        float4 ww[4];
        int4 pp[4];
        bool fast = true;
        #pragma unroll
        for (int q = 0; q < 4; q++) {
            pp[q] = pm4[q];
            ww[q] = w4[q];
            int e = base + 4 * q;
            fast = fast && (pp[q].x == e) && (pp[q].y == e + 1) &&
                   (pp[q].z == e + 2) && (pp[q].w == e + 3);
        }
        float acc[4] = {0.f, 0.f, 0.f, 0.f};
        if (fast) {
            #pragma unroll
            for (int p = 0; p < 4; p++) {
                const float4* xp = (const float4*)(x + (long long)(b0 + p) * NPIX + base);
                #pragma unroll
                for (int q = 0; q < 4; q++) {
                    float4 xv = xp[q];
                    acc[p] += xv.x * ww[q].x + xv.y * ww[q].y +
                              xv.z * ww[q].z + xv.w * ww[q].w;
                }
            }
        } else {
            #pragma unroll
            for (int p = 0; p < 4; p++) {
                const float* xb = x + (long long)(b0 + p) * NPIX;
                #pragma unroll
                for (int q = 0; q < 4; q++) {
                    acc[p] += xb[pp[q].x] * ww[q].x + xb[pp[q].y] * ww[q].y +
                              xb[pp[q].z] * ww[q].z + xb[pp[q].w] * ww[q].w;
                }
            }
        }
        float br = b_ret[n];
        float sl = 0.f;
        {
            const float4* wl = (const float4*)(w_lgn + base);
            #pragma unroll
            for (int q = 0; q < 4; q++) {
                float4 v = wl[q];
                sl += v.x + v.y + v.z + v.w;
            }
        }
        float bl = b_lgn[n];
        #pragma unroll
        for (int p = 0; p < 4; p++) {
            float r1 = sigmoidf_(acc[p] - br);
            s[lane][w * 4 + p] = sigmoidf_(r1 * sl - bl);
        }
        __syncthreads();
        #pragma unroll
        for (int i = 0; i < 4; i++) {
            int id = t + i * 256;
            int n_o = id >> 5, b_o = id & 31;
            r2t[(long long)(bn * 32 + n_o) * BATCH + bb * 32 + b_o] =
                __float2half(s[n_o][b_o]);
        }
        return;
    }
    blk -= RET_BLKS;
    if (blk < CSR1_BLKS) {
        csr_row(m1, NLGN, MAX1, idx1, cnt1, blk * 8 + w, lane);
        return;
    }
    blk -= CSR1_BLKS;
    if (blk < CSR2_BLKS) {
        csr_row(m2, NV1, MAX2, idx2, cnt2, blk * 8 + w, lane);
        return;
    }
    blk -= CSR2_BLKS;
    if (blk < SUMS_BLKS) {
        int i = blk * 256 + t;
        if (i < NRET) {
            float s2 = 0.f;
            #pragma unroll
            for (int k = 0; k < 16; k++) s2 += w_lgn[i * 16 + k];
            sums[i] = s2;
        } else if (i < NRET + NV1) {
            int j = i - NRET;
            float s2 = 0.f;
            #pragma unroll
            for (int k = 0; k < 32; k++) s2 += w_v1[j * 32 + k];
            sums[NRET + j] = s2;
        } else if (i < NRET + NV1 + NIT) {
            int j = i - NRET - NV1;
            float s2 = 0.f;
            #pragma unroll
            for (int k = 0; k < 32; k++) s2 += w_it[j * 32 + k];
            sums[NRET + NV1 + j] = s2;
        }
        return;
    }
    blk -= SUMS_BLKS;
    {
        int row0 = blk * 4;
        #pragma unroll
        for (int rr = 0; rr < 4; rr++) {
            int r = row0 + rr;
            long long rb = (long long)r * NK;
            #pragma unroll
            for (int i = 0; i < NK / 256; i++) {
                int col = i * 256 + t;
                float v = (r < NCLS) ? W_cls[rb + col] : 0.f;
                __nv_bfloat16 hi = __float2bfloat16(v);
                __nv_bfloat16 lo = __float2bfloat16(v - __bfloat162float(hi));
                whi[rb + col] = hi;
                wlo[rb + col] = lo;
            }
        }
    }
}

// ---------------- SpMM kernels ----------------
__global__ void spmm_act_h2h(const int* __restrict__ idx,
                             const int* __restrict__ cnt, int maxnnz,
                             const __half2* __restrict__ src2,
                             const float* __restrict__ s,
                             const float* __restrict__ bias,
                             __half2* __restrict__ dst2) {
    int j = blockIdx.x * 2 + (threadIdx.x >> 7);
    int b2 = threadIdx.x & 127;
    int n = cnt[j];
    const int* ji = idx + (long long)j * maxnnz;
    float ax = 0.f, ay = 0.f, cx = 0.f, cy = 0.f;
    int k = 0;
    for (; k + 8 <= n; k += 8) {
        float2 v0 = __half22float2(src2[ji[k+0] * (BATCH/2) + b2]);
        float2 v1 = __half22float2(src2[ji[k+1] * (BATCH/2) + b2]);
        float2 v2 = __half22float2(src2[ji[k+2] * (BATCH/2) + b2]);
        float2 v3 = __half22float2(src2[ji[k+3] * (BATCH/2) + b2]);
        float2 v4 = __half22float2(src2[ji[k+4] * (BATCH/2) + b2]);
        float2 v5 = __half22float2(src2[ji[k+5] * (BATCH/2) + b2]);
        float2 v6 = __half22float2(src2[ji[k+6] * (BATCH/2) + b2]);
        float2 v7 = __half22float2(src2[ji[k+7] * (BATCH/2) + b2]);
        ax += (v0.x + v1.x) + (v2.x + v3.x);
        ay += (v0.y + v1.y) + (v2.y + v3.y);
        cx += (v4.x + v5.x) + (v6.x + v7.x);
        cy += (v4.y + v5.y) + (v6.y + v7.y);
    }
    for (; k < n; k++) {
        float2 v = __half22float2(src2[ji[k] * (BATCH/2) + b2]);
        ax += v.x; ay += v.y;
    }
    ax += cx; ay += cy;
    float sj = s[j], bj = bias[j], fn = (float)n;
    float ox = sigmoidf_((ax / fn) * sj - bj);
    float oy = sigmoidf_((ay / fn) * sj - bj);
    dst2[(long long)j * (BATCH/2) + b2] = __floats2half2_rn(ox, oy);
}

__global__ void spmm_act_h2f(const int* __restrict__ idx,
                             const int* __restrict__ cnt, int maxnnz,
                             const __half2* __restrict__ src2,
                             const float* __restrict__ s,
                             const float* __restrict__ bias,
                             float* __restrict__ dst) {
    int j = blockIdx.x * 2 + (threadIdx.x >> 7);
    int b2 = threadIdx.x & 127;
    int n = cnt[j];
    const int* ji = idx + (long long)j * maxnnz;
    float ax = 0.f, ay = 0.f, cx = 0.f, cy = 0.f;
    int k = 0;
    for (; k + 8 <= n; k += 8) {
        float2 v0 = __half22float2(src2[ji[k+0] * (BATCH/2) + b2]);
        float2 v1 = __half22float2(src2[ji[k+1] * (BATCH/2) + b2]);
        float2 v2 = __half22float2(src2[ji[k+2] * (BATCH/2) + b2]);
        float2 v3 = __half22float2(src2[ji[k+3] * (BATCH/2) + b2]);
        float2 v4 = __half22float2(src2[ji[k+4] * (BATCH/2) + b2]);
        float2 v5 = __half22float2(src2[ji[k+5] * (BATCH/2) + b2]);
        float2 v6 = __half22float2(src2[ji[k+6] * (BATCH/2) + b2]);
        float2 v7 = __half22float2(src2[ji[k+7] * (BATCH/2) + b2]);
        ax += (v0.x + v1.x) + (v2.x + v3.x);
        ay += (v0.y + v1.y) + (v2.y + v3.y);
        cx += (v4.x + v5.x) + (v6.x + v7.x);
        cy += (v4.y + v5.y) + (v6.y + v7.y);
    }
    for (; k < n; k++) {
        float2 v = __half22float2(src2[ji[k] * (BATCH/2) + b2]);
        ax += v.x; ay += v.y;
    }
    ax += cx; ay += cy;
    float sj = s[j], bj = bias[j], fn = (float)n;
    float2 o;
    o.x = sigmoidf_((ax / fn) * sj - bj);
    o.y = sigmoidf_((ay / fn) * sj - bj);
    *(float2*)(dst + (long long)j * BATCH + 2 * b2) = o;
}

// ---------------- acts transpose + bf16 hi/lo split ----------------
__global__ void prep_acts_kernel(const float* __restrict__ r4t,
                                 __nv_bfloat16* __restrict__ ahi,
                                 __nv_bfloat16* __restrict__ alo) {
    __shared__ float s[32][33];
    int t = threadIdx.x;
    int k0 = blockIdx.x * 32;
    int b0 = blockIdx.y * 32;
    #pragma unroll
    for (int i = 0; i < 4; i++) {
        int u = t + i * 256;
        s[u >> 5][u & 31] = r4t[(long long)(k0 + (u >> 5)) * BATCH + b0 + (u & 31)];
    }
    __syncthreads();
    int b_loc = t >> 3;
    int kq = (t & 7) * 4;
    long long base = (long long)(b0 + b_loc) * NK + k0 + kq;
    #pragma unroll
    for (int j2 = 0; j2 < 4; j2++) {
        float v = s[kq + j2][b_loc];
        __nv_bfloat16 hi = __float2bfloat16(v);
        __nv_bfloat16 lo = __float2bfloat16(v - __bfloat162float(hi));
        ahi[base + j2] = hi;
        alo[base + j2] = lo;
    }
}

// ---------------- classifier GEMM via mma.sync + ldmatrix ------------------
// CTA tile 128c x 64b, k-chunk 32, 8 warps (4c x 2b), warp tile 32c x 32b.
#define KCH       (NK / KSPLIT / 32)     // 12
#define SROW      80
#define WHI_OFF   0
#define WLO_OFF   (128 * SROW)           // 10240
#define AHI_OFF   (2 * 128 * SROW)       // 20480
#define ALO_OFF   (AHI_OFF + 64 * SROW)  // 25600
#define STAGE2_B  (ALO_OFF + 64 * SROW)  // 30720
#define GEMM2_SMEM (2 * STAGE2_B)        // 61440

__global__ void __launch_bounds__(256, 2)
cls_gemm_mma(const __nv_bfloat16* __restrict__ whi,
             const __nv_bfloat16* __restrict__ wlo,
             const __nv_bfloat16* __restrict__ ahi,
             const __nv_bfloat16* __restrict__ alo,
             float* __restrict__ part) {
    extern __shared__ char sm[];
    int t = threadIdx.x;
    int lane = t & 31, wid = t >> 5;
    int gid = lane >> 2, tig = lane & 3;
    int wm = wid & 3, wn = wid >> 2;
    int c0 = blockIdx.x * 128, b0 = blockIdx.y * 64, ks = blockIdx.z;
    int kbase = ks * (NK / KSPLIT);

    int r = t >> 2, q = t & 3;           // loader role
    float acc[2][4][4];
    #pragma unroll
    for (int i = 0; i < 2; i++)
        #pragma unroll
        for (int j = 0; j < 4; j++)
            #pragma unroll
            for (int e = 0; e < 4; e++) acc[i][j][e] = 0.f;

    // ldmatrix per-lane address components (hoisted)
    int lr = lane & 7, grp = lane >> 3;
    uint32_t smb = smem_u32(sm);
    // W: m0 rows+0 @kb, m1 rows+8 @kb, m2 rows+0 @kb+16, m3 rows+8 @kb+16
    uint32_t w_off = (uint32_t)((wm * 32 + (grp & 1) * 8 + lr) * SROW +
                                (grp >> 1) * 16);
    // B: m0 ahi @kb, m1 ahi @kb+16, m2 alo @kb, m3 alo @kb+16
    uint32_t b_off = (uint32_t)((wn * 32 + lr) * SROW + (grp & 1) * 16) +
                     ((grp >> 1) ? ALO_OFF : AHI_OFF);

    int4 rg[6];
    #define LOAD_CHUNK(K0) do {                                               \
        long long wo0 = ((long long)(c0 + r) * NK + (K0)) * 2 + q * 16;       \
        long long wo1 = ((long long)(c0 + r + 64) * NK + (K0)) * 2 + q * 16;  \
        long long ao  = ((long long)(b0 + r) * NK + (K0)) * 2 + q * 16;       \
        rg[0] = *(const int4*)((const char*)whi + wo0);                       \
        rg[1] = *(const int4*)((const char*)whi + wo1);                       \
        rg[2] = *(const int4*)((const char*)wlo + wo0);                       \
        rg[3] = *(const int4*)((const char*)wlo + wo1);                       \
        rg[4] = *(const int4*)((const char*)ahi + ao);                        \
        rg[5] = *(const int4*)((const char*)alo + ao);                        \
    } while (0)
    #define STORE_CHUNK(BUF) do {                                             \
        char* s_ = sm + (BUF) * STAGE2_B;                                     \
        *(int4*)(s_ + WHI_OFF + r * SROW + q * 16) = rg[0];                   \
        *(int4*)(s_ + WHI_OFF + (r + 64) * SROW + q * 16) = rg[1];            \
        *(int4*)(s_ + WLO_OFF + r * SROW + q * 16) = rg[2];                   \
        *(int4*)(s_ + WLO_OFF + (r + 64) * SROW + q * 16) = rg[3];            \
        *(int4*)(s_ + AHI_OFF + r * SROW + q * 16) = rg[4];                   \
        *(int4*)(s_ + ALO_OFF + r * SROW + q * 16) = rg[5];                   \
    } while (0)

    LOAD_CHUNK(kbase);
    STORE_CHUNK(0);
    __syncthreads();

    for (int j = 0; j < KCH; j++) {
        if (j + 1 < KCH) LOAD_CHUNK(kbase + (j + 1) * 32);
        uint32_t sb = smb + (j & 1) * STAGE2_B;
        #pragma unroll
        for (int s = 0; s < 2; s++) {
            uint32_t kb2 = s * 32;
            uint32_t wa[2][4], wl[2][4];
            #pragma unroll
            for (int i = 0; i < 2; i++) {
                ldsm_x4(wa[i], sb + WHI_OFF + w_off + i * 16 * SROW + kb2);
                ldsm_x4(wl[i], sb + WLO_OFF + w_off + i * 16 * SROW + kb2);
            }
            #pragma unroll
            for (int jj = 0; jj < 4; jj++) {
                uint32_t bf[4];  // bh0, bh1, bl0, bl1
                ldsm_x4(bf, sb + b_off + jj * 8 * SROW + kb2);
                mma16816(acc[0][jj], wa[0], bf);
                mma16816(acc[1][jj], wa[1], bf);
                mma16816(acc[0][jj], wa[0], bf + 2);
                mma16816(acc[1][jj], wa[1], bf + 2);
                mma16816(acc[0][jj], wl[0], bf);
                mma16816(acc[1][jj], wl[1], bf);
            }
        }
        if (j + 1 < KCH) STORE_CHUNK((j + 1) & 1);
        __syncthreads();
    }

    #pragma unroll
    for (int i = 0; i < 2; i++) {
        int c = c0 + wm * 32 + i * 16 + gid;
        #pragma unroll
        for (int jj = 0; jj < 4; jj++) {
            int b = b0 + wn * 32 + jj * 8 + 2 * tig;
            float2 lo = make_float2(acc[i][jj][0], acc[i][jj][1]);
            float2 hi = make_float2(acc[i][jj][2], acc[i][jj][3]);
            *(float2*)(part + ((long long)ks * NCLSP + c) * BATCH + b) = lo;
            *(float2*)(part + ((long long)ks * NCLSP + c + 8) * BATCH + b) = hi;
        }
    }
    #undef LOAD_CHUNK
    #undef STORE_CHUNK
}

// ---------------- split-K reduce + bias ----------------
__global__ void reduce_kernel(const float* __restrict__ part,
                              const float* __restrict__ b_cls,
                              float* __restrict__ out) {
    int id = blockIdx.x * blockDim.x + threadIdx.x;
    int b = id & (BATCH - 1);
    int c = id >> 8;
    if (c >= NCLS) return;
    float acc = b_cls[c];
    #pragma unroll
    for (int ks = 0; ks < KSPLIT; ks++)
        acc += part[((long long)ks * NCLSP + c) * BATCH + b];
    out[(long long)b * NCLS + c] = acc;
}

// ---------------- launch ----------------
extern "C" void kernel_launch(void* const* d_in, const int* in_sizes, int n_in,
                              void* d_out, int out_size) {
    const float* x        = (const float*)d_in[0];
    const float* w_ret    = (const float*)d_in[1];
    const float* b_ret    = (const float*)d_in[2];
    const float* w_lgn    = (const float*)d_in[3];
    const float* b_lgn    = (const float*)d_in[4];
    const float* w_v1     = (const float*)d_in[5];
    const float* b_v1     = (const float*)d_in[6];
    const float* w_it     = (const float*)d_in[7];
    const float* b_it     = (const float*)d_in[8];
    const float* W_cls    = (const float*)d_in[9];
    const float* b_cls    = (const float*)d_in[10];
    const int*   pixel_map= (const int*)d_in[11];
    const int*   m1       = (const int*)d_in[12];
    const int*   m2       = (const int*)d_in[13];
    float* out = (float*)d_out;

    __half2* r2t2 = nullptr; __half2* r3t2 = nullptr; float* r4t = nullptr;
    float* sums = nullptr; float* partp = nullptr;
    int *idx1 = nullptr, *cnt1 = nullptr, *idx2 = nullptr, *cnt2 = nullptr;
    __nv_bfloat16 *whi = nullptr, *wlo = nullptr, *ahi = nullptr, *alo = nullptr;
    cudaGetSymbolAddress((void**)&r2t2, g_r2t2);
    cudaGetSymbolAddress((void**)&r3t2, g_r3t2);
    cudaGetSymbolAddress((void**)&r4t,  g_r4t);
    cudaGetSymbolAddress((void**)&sums, g_sums);
    cudaGetSymbolAddress((void**)&partp,g_part);
    cudaGetSymbolAddress((void**)&idx1, g_idx1);
    cudaGetSymbolAddress((void**)&cnt1, g_cnt1);
    cudaGetSymbolAddress((void**)&idx2, g_idx2);
    cudaGetSymbolAddress((void**)&cnt2, g_cnt2);
    cudaGetSymbolAddress((void**)&whi,  g_whi);
    cudaGetSymbolAddress((void**)&wlo,  g_wlo);
    cudaGetSymbolAddress((void**)&ahi,  g_ahi);
    cudaGetSymbolAddress((void**)&alo,  g_alo);

    cudaFuncSetAttribute(cls_gemm_mma,
                         cudaFuncAttributeMaxDynamicSharedMemorySize, GEMM2_SMEM);

    // phase 1: retina+LGN, CSR builds, weight sums, W bf16 split
    {
        int nblk = RET_BLKS + CSR1_BLKS + CSR2_BLKS + SUMS_BLKS + WPREP_BLKS;
        phase1_kernel<<<nblk, 256>>>(x, pixel_map, w_ret, b_ret, w_lgn, b_lgn,
                                     w_v1, w_it, W_cls, m1, m2, (__half*)r2t2,
                                     sums, idx1, cnt1, idx2, cnt2, whi, wlo);
    }
    // V1
    spmm_act_h2h<<<NV1 / 2, 256>>>(idx1, cnt1, MAX1, r2t2,
                                   sums + NRET, b_v1, r3t2);
    // IT
    spmm_act_h2f<<<NIT / 2, 256>>>(idx2, cnt2, MAX2, r3t2,
                                   sums + NRET + NV1, b_it, r4t);
    // acts transpose + split
    {
        dim3 grid(NK / 32, BATCH / 32);
        prep_acts_kernel<<<grid, 256>>>(r4t, ahi, alo);
    }
    // classifier on tensor cores (mma.sync + ldmatrix)
    {
        dim3 grid(NCLSP / 128, BATCH / 64, KSPLIT);
        cls_gemm_mma<<<grid, 256, GEMM2_SMEM>>>(whi, wlo, ahi, alo, partp);
    }
    reduce_kernel<<<(NCLSP * BATCH + 255) / 256, 256>>>(partp, b_cls, out);
    (void)in_sizes; (void)n_in; (void)out_size;
}

// round 15
// speedup vs baseline: 1.1252x; 1.0350x over previous
#include <cuda_runtime.h>
#include <cuda_fp16.h>
#include <cuda_bf16.h>
#include <cstdint>

// ---------------- problem constants ----------------
#define BATCH  256
#define NPIX   49152
#define NRET   3072
#define NLGN   3072
#define NV1    6144
#define NIT    3072
#define NCLS   1000
#define NCLSP  1024
#define NK     NIT

#define MAX1   128
#define MAX2   256
#define KSPLIT 8

// phase-1 block roles: retina + CSR1 + sums (only what V1 SpMM needs)
#define RET_BX   96
#define RET_BY   8
#define RET_BLKS (RET_BX * RET_BY)       // 768
#define CSR1_BLKS (NV1 / 8)              // 768
#define SUMS_BLKS ((NRET + NV1 + NIT + 255) / 256)  // 48
// phase-2 block roles: V1 SpMM + CSR2 + W-prep
#define SPMM1_BLKS (NV1 / 2)             // 3072
#define CSR2_BLKS (NIT / 8)              // 384
#define WPREP_BLKS (NCLSP / 4)           // 256

// ---------------- device scratch ----------------
__device__ __half2       g_r2t2[NRET * BATCH / 2];
__device__ __half2       g_r3t2[NV1 * BATCH / 2];
__device__ float         g_sums[NRET + NV1 + NIT];
__device__ int           g_idx1[NV1 * MAX1];
__device__ int           g_cnt1[NV1];
__device__ int           g_idx2[NIT * MAX2];
__device__ int           g_cnt2[NIT];
__device__ float         g_part[KSPLIT * NCLSP * BATCH];
__device__ __nv_bfloat16 g_whi[NCLSP * NK];           // W hi, [c, k]
__device__ __nv_bfloat16 g_wlo[NCLSP * NK];           // W lo
__device__ __nv_bfloat16 g_ahi[NIT * BATCH];          // acts hi, [k, b]
__device__ __nv_bfloat16 g_alo[NIT * BATCH];          // acts lo, [k, b]

__device__ __forceinline__ float sigmoidf_(float z) {
    return 1.0f / (1.0f + __expf(-z));
}

// ---------------- warp MMA + ldmatrix ----------------
__device__ __forceinline__ void mma16816(float* c, const uint32_t* a,
                                         const uint32_t* b) {
    asm volatile(
        "mma.sync.aligned.m16n8k16.row.col.f32.bf16.bf16.f32 "
        "{%0,%1,%2,%3}, {%4,%5,%6,%7}, {%8,%9}, {%0,%1,%2,%3};"
        : "+f"(c[0]), "+f"(c[1]), "+f"(c[2]), "+f"(c[3])
        : "r"(a[0]), "r"(a[1]), "r"(a[2]), "r"(a[3]),
          "r"(b[0]), "r"(b[1]));
}
__device__ __forceinline__ void ldsm_x4(uint32_t* r, uint32_t addr) {
    asm volatile(
        "ldmatrix.sync.aligned.m8n8.x4.shared.b16 {%0,%1,%2,%3}, [%4];"
        : "=r"(r[0]), "=r"(r[1]), "=r"(r[2]), "=r"(r[3]) : "r"(addr));
}
__device__ __forceinline__ void ldsm_x4_t(uint32_t* r, uint32_t addr) {
    asm volatile(
        "ldmatrix.sync.aligned.m8n8.x4.trans.shared.b16 {%0,%1,%2,%3}, [%4];"
        : "=r"(r[0]), "=r"(r[1]), "=r"(r[2]), "=r"(r[3]) : "r"(addr));
}
__device__ __forceinline__ uint32_t smem_u32(const void* p) {
    uint32_t a;
    asm("{ .reg .u64 t; cvta.to.shared.u64 t, %1; cvt.u32.u64 %0, t; }"
        : "=r"(a) : "l"(p));
    return a;
}

// ---------------- CSR build role ----------------
__device__ __forceinline__ void csr_row(const int* __restrict__ m, int cols,
                                        int maxnnz, int* __restrict__ idx,
                                        int* __restrict__ cnt, int row, int lane) {
    const int4* row4 = (const int4*)(m + (long long)row * cols);
    int* out = idx + (long long)row * maxnnz;
    unsigned lt = (1u << lane) - 1;
    int c = 0;
    int iters = cols >> 7;
    for (int it = 0; it < iters; it++) {
        int4 v = row4[it * 32 + lane];
        int cbase = it * 128 + 4 * lane;
        #pragma unroll
        for (int e = 0; e < 4; e++) {
            int val = (e == 0) ? v.x : (e == 1) ? v.y : (e == 2) ? v.z : v.w;
            unsigned msk = __ballot_sync(0xffffffffu, val != 0);
            if (val) {
                int pos = c + __popc(msk & lt);
                if (pos < maxnnz) out[pos] = cbase + e;
            }
            c += __popc(msk);
        }
    }
    if (lane == 0) cnt[row] = (c < maxnnz) ? c : maxnnz;
}

// ---------------- phase-1: retina+LGN, CSR1, weight sums ----------------
__global__ void phase1_kernel(const float* __restrict__ x,
                              const int* __restrict__ pm,
                              const float* __restrict__ w_ret,
                              const float* __restrict__ b_ret,
                              const float* __restrict__ w_lgn,
                              const float* __restrict__ b_lgn,
                              const float* __restrict__ w_v1,
                              const float* __restrict__ w_it,
                              const int* __restrict__ m1,
                              __half* __restrict__ r2t,
                              float* __restrict__ sums,
                              int* __restrict__ idx1, int* __restrict__ cnt1) {
    int blk = blockIdx.x;
    int t = threadIdx.x;
    int lane = t & 31;
    int w = t >> 5;

    if (blk < RET_BLKS) {
        __shared__ float s[32][33];
        int bn = blk % RET_BX;
        int bb = blk / RET_BX;
        int n = bn * 32 + lane;
        int b0 = bb * 32 + w * 4;
        int base = n * 16;

        const int4*   pm4 = (const int4*)(pm + base);
        const float4* w4  = (const float4*)(w_ret + base);
        float4 ww[4];
        int4 pp[4];
        bool fast = true;
        #pragma unroll
        for (int q = 0; q < 4; q++) {
            pp[q] = pm4[q];
            ww[q] = w4[q];
            int e = base + 4 * q;
            fast = fast && (pp[q].x == e) && (pp[q].y == e + 1) &&
                   (pp[q].z == e + 2) && (pp[q].w == e + 3);
        }
        float acc[4] = {0.f, 0.f, 0.f, 0.f};
        if (fast) {
            #pragma unroll
            for (int p = 0; p < 4; p++) {
                const float4* xp = (const float4*)(x + (long long)(b0 + p) * NPIX + base);
                #pragma unroll
                for (int q = 0; q < 4; q++) {
                    float4 xv = xp[q];
                    acc[p] += xv.x * ww[q].x + xv.y * ww[q].y +
                              xv.z * ww[q].z + xv.w * ww[q].w;
                }
            }
        } else {
            #pragma unroll
            for (int p = 0; p < 4; p++) {
                const float* xb = x + (long long)(b0 + p) * NPIX;
                #pragma unroll
                for (int q = 0; q < 4; q++) {
                    acc[p] += xb[pp[q].x] * ww[q].x + xb[pp[q].y] * ww[q].y +
                              xb[pp[q].z] * ww[q].z + xb[pp[q].w] * ww[q].w;
                }
            }
        }
        float br = b_ret[n];
        float sl = 0.f;
        {
            const float4* wl = (const float4*)(w_lgn + base);
            #pragma unroll
            for (int q = 0; q < 4; q++) {
                float4 v = wl[q];
                sl += v.x + v.y + v.z + v.w;
            }
        }
        float bl = b_lgn[n];
        #pragma unroll
        for (int p = 0; p < 4; p++) {
            float r1 = sigmoidf_(acc[p] - br);
            s[lane][w * 4 + p] = sigmoidf_(r1 * sl - bl);
        }
        __syncthreads();
        #pragma unroll
        for (int i = 0; i < 4; i++) {
            int id = t + i * 256;
            int n_o = id >> 5, b_o = id & 31;
            r2t[(long long)(bn * 32 + n_o) * BATCH + bb * 32 + b_o] =
                __float2half(s[n_o][b_o]);
        }
        return;
    }
    blk -= RET_BLKS;
    if (blk < CSR1_BLKS) {
        csr_row(m1, NLGN, MAX1, idx1, cnt1, blk * 8 + w, lane);
        return;
    }
    blk -= CSR1_BLKS;
    {
        int i = blk * 256 + t;
        if (i < NRET) {
            float s2 = 0.f;
            #pragma unroll
            for (int k = 0; k < 16; k++) s2 += w_lgn[i * 16 + k];
            sums[i] = s2;
        } else if (i < NRET + NV1) {
            int j = i - NRET;
            float s2 = 0.f;
            #pragma unroll
            for (int k = 0; k < 32; k++) s2 += w_v1[j * 32 + k];
            sums[NRET + j] = s2;
        } else if (i < NRET + NV1 + NIT) {
            int j = i - NRET - NV1;
            float s2 = 0.f;
            #pragma unroll
            for (int k = 0; k < 32; k++) s2 += w_it[j * 32 + k];
            sums[NRET + NV1 + j] = s2;
        }
    }
}

// ---------------- phase-2: V1 SpMM + CSR2 build + W-prep ----------------
__global__ void phase2_kernel(const int* __restrict__ idx,
                              const int* __restrict__ cnt,
                              const __half2* __restrict__ src2,
                              const float* __restrict__ s,
                              const float* __restrict__ bias,
                              __half2* __restrict__ dst2,
                              const int* __restrict__ m2,
                              int* __restrict__ idx2, int* __restrict__ cnt2,
                              const float* __restrict__ W_cls,
                              __nv_bfloat16* __restrict__ whi,
                              __nv_bfloat16* __restrict__ wlo) {
    int blk = blockIdx.x;
    int t = threadIdx.x;
    if (blk < SPMM1_BLKS) {
        int j = blk * 2 + (t >> 7);
        int b2 = t & 127;
        int n = cnt[j];
        const int* ji = idx + (long long)j * MAX1;
        float ax = 0.f, ay = 0.f, cx = 0.f, cy = 0.f;
        int k = 0;
        for (; k + 8 <= n; k += 8) {
            float2 v0 = __half22float2(src2[ji[k+0] * (BATCH/2) + b2]);
            float2 v1 = __half22float2(src2[ji[k+1] * (BATCH/2) + b2]);
            float2 v2 = __half22float2(src2[ji[k+2] * (BATCH/2) + b2]);
            float2 v3 = __half22float2(src2[ji[k+3] * (BATCH/2) + b2]);
            float2 v4 = __half22float2(src2[ji[k+4] * (BATCH/2) + b2]);
            float2 v5 = __half22float2(src2[ji[k+5] * (BATCH/2) + b2]);
            float2 v6 = __half22float2(src2[ji[k+6] * (BATCH/2) + b2]);
            float2 v7 = __half22float2(src2[ji[k+7] * (BATCH/2) + b2]);
            ax += (v0.x + v1.x) + (v2.x + v3.x);
            ay += (v0.y + v1.y) + (v2.y + v3.y);
            cx += (v4.x + v5.x) + (v6.x + v7.x);
            cy += (v4.y + v5.y) + (v6.y + v7.y);
        }
        for (; k < n; k++) {
            float2 v = __half22float2(src2[ji[k] * (BATCH/2) + b2]);
            ax += v.x; ay += v.y;
        }
        ax += cx; ay += cy;
        float sj = s[j], bj = bias[j], fn = (float)n;
        float ox = sigmoidf_((ax / fn) * sj - bj);
        float oy = sigmoidf_((ay / fn) * sj - bj);
        dst2[(long long)j * (BATCH/2) + b2] = __floats2half2_rn(ox, oy);
        return;
    }
    blk -= SPMM1_BLKS;
    int lane = t & 31, w = t >> 5;
    if (blk < CSR2_BLKS) {
        csr_row(m2, NV1, MAX2, idx2, cnt2, blk * 8 + w, lane);
        return;
    }
    blk -= CSR2_BLKS;
    {
        int row0 = blk * 4;
        #pragma unroll
        for (int rr = 0; rr < 4; rr++) {
            int r = row0 + rr;
            long long rb = (long long)r * NK;
            #pragma unroll
            for (int i = 0; i < NK / 256; i++) {
                int col = i * 256 + t;
                float v = (r < NCLS) ? W_cls[rb + col] : 0.f;
                __nv_bfloat16 hi = __float2bfloat16(v);
                __nv_bfloat16 lo = __float2bfloat16(v - __bfloat162float(hi));
                whi[rb + col] = hi;
                wlo[rb + col] = lo;
            }
        }
    }
}

// ---------------- phase-3: IT SpMM, writes bf16 hi/lo [k,b] directly -------
__global__ void spmm_it_kernel(const int* __restrict__ idx,
                               const int* __restrict__ cnt,
                               const __half2* __restrict__ src2,
                               const float* __restrict__ s,
                               const float* __restrict__ bias,
                               __nv_bfloat162* __restrict__ ahi2,
                               __nv_bfloat162* __restrict__ alo2) {
    int j = blockIdx.x * 2 + (threadIdx.x >> 7);
    int b2 = threadIdx.x & 127;
    int n = cnt[j];
    const int* ji = idx + (long long)j * MAX2;
    float ax = 0.f, ay = 0.f, cx = 0.f, cy = 0.f;
    int k = 0;
    for (; k + 8 <= n; k += 8) {
        float2 v0 = __half22float2(src2[ji[k+0] * (BATCH/2) + b2]);
        float2 v1 = __half22float2(src2[ji[k+1] * (BATCH/2) + b2]);
        float2 v2 = __half22float2(src2[ji[k+2] * (BATCH/2) + b2]);
        float2 v3 = __half22float2(src2[ji[k+3] * (BATCH/2) + b2]);
        float2 v4 = __half22float2(src2[ji[k+4] * (BATCH/2) + b2]);
        float2 v5 = __half22float2(src2[ji[k+5] * (BATCH/2) + b2]);
        float2 v6 = __half22float2(src2[ji[k+6] * (BATCH/2) + b2]);
        float2 v7 = __half22float2(src2[ji[k+7] * (BATCH/2) + b2]);
        ax += (v0.x + v1.x) + (v2.x + v3.x);
        ay += (v0.y + v1.y) + (v2.y + v3.y);
        cx += (v4.x + v5.x) + (v6.x + v7.x);
        cy += (v4.y + v5.y) + (v6.y + v7.y);
    }
    for (; k < n; k++) {
        float2 v = __half22float2(src2[ji[k] * (BATCH/2) + b2]);
        ax += v.x; ay += v.y;
    }
    ax += cx; ay += cy;
    float sj = s[j], bj = bias[j], fn = (float)n;
    float ox = sigmoidf_((ax / fn) * sj - bj);
    float oy = sigmoidf_((ay / fn) * sj - bj);
    __nv_bfloat16 hx = __float2bfloat16(ox);
    __nv_bfloat16 hy = __float2bfloat16(oy);
    __nv_bfloat16 lx = __float2bfloat16(ox - __bfloat162float(hx));
    __nv_bfloat16 ly = __float2bfloat16(oy - __bfloat162float(hy));
    long long o = (long long)j * (BATCH / 2) + b2;
    ahi2[o] = __halves2bfloat162(hx, hy);
    alo2[o] = __halves2bfloat162(lx, ly);
}

// ---------------- classifier GEMM: mma.sync + ldmatrix(+trans) -------------
// CTA tile 128c x 64b, k-chunk 32, 8 warps (4c x 2b), warp tile 32c x 32b.
// W from [c,k] bf16 (SROW rows); A from [k,b] bf16 via ldmatrix.trans (AROW rows).
#define KCH       (NK / KSPLIT / 32)     // 12
#define SROW      80
#define WHI_OFF   0
#define WLO_OFF   (128 * SROW)           // 10240
#define AROW      144
#define AHI2_OFF  (2 * 128 * SROW)       // 20480
#define ALO2_OFF  (AHI2_OFF + 32 * AROW) // 25088
#define STAGE3_B  (ALO2_OFF + 32 * AROW) // 29696
#define GEMM3_SMEM (2 * STAGE3_B)        // 59392

__global__ void __launch_bounds__(256, 2)
cls_gemm_mma(const __nv_bfloat16* __restrict__ whi,
             const __nv_bfloat16* __restrict__ wlo,
             const __nv_bfloat16* __restrict__ ahi,
             const __nv_bfloat16* __restrict__ alo,
             float* __restrict__ part) {
    extern __shared__ char sm[];
    int t = threadIdx.x;
    int lane = t & 31, wid = t >> 5;
    int gid = lane >> 2, tig = lane & 3;
    int wm = wid & 3, wn = wid >> 2;
    int c0 = blockIdx.x * 128, b0 = blockIdx.y * 64, ks = blockIdx.z;
    int kbase = ks * (NK / KSPLIT);

    int r = t >> 2, q = t & 3;           // W loader role
    int row2 = t >> 3, colq = t & 7;     // A loader role
    float acc[2][4][4];
    #pragma unroll
    for (int i = 0; i < 2; i++)
        #pragma unroll
        for (int j = 0; j < 4; j++)
            #pragma unroll
            for (int e = 0; e < 4; e++) acc[i][j][e] = 0.f;

    // ldmatrix per-lane address components (hoisted)
    int lr = lane & 7, grp = lane >> 3;
    uint32_t smb = smem_u32(sm);
    // W (non-trans): m0 rows+0 @kb, m1 rows+8 @kb, m2 rows+0 @kb+16, m3 rows+8 @kb+16
    uint32_t w_off = (uint32_t)((wm * 32 + (grp & 1) * 8 + lr) * SROW +
                                (grp >> 1) * 16);
    // A (trans, [k][b]): m0 hi k+0..7, m1 hi k+8..15, m2 lo k+0..7, m3 lo k+8..15
    uint32_t a_off = ((grp >> 1) ? ALO2_OFF : AHI2_OFF) +
                     (uint32_t)(((grp & 1) * 8 + lr) * AROW + wn * 32 * 2);

    int4 rg[6];
    #define LOAD_CHUNK(K0) do {                                               \
        long long wo0 = ((long long)(c0 + r) * NK + (K0)) * 2 + q * 16;       \
        long long wo1 = ((long long)(c0 + r + 64) * NK + (K0)) * 2 + q * 16;  \
        long long ao  = ((long long)((K0) + row2) * BATCH + b0 + colq * 8) * 2; \
        rg[0] = *(const int4*)((const char*)whi + wo0);                       \
        rg[1] = *(const int4*)((const char*)whi + wo1);                       \
        rg[2] = *(const int4*)((const char*)wlo + wo0);                       \
        rg[3] = *(const int4*)((const char*)wlo + wo1);                       \
        rg[4] = *(const int4*)((const char*)ahi + ao);                        \
        rg[5] = *(const int4*)((const char*)alo + ao);                        \
    } while (0)
    #define STORE_CHUNK(BUF) do {                                             \
        char* s_ = sm + (BUF) * STAGE3_B;                                     \
        *(int4*)(s_ + WHI_OFF + r * SROW + q * 16) = rg[0];                   \
        *(int4*)(s_ + WHI_OFF + (r + 64) * SROW + q * 16) = rg[1];            \
        *(int4*)(s_ + WLO_OFF + r * SROW + q * 16) = rg[2];                   \
        *(int4*)(s_ + WLO_OFF + (r + 64) * SROW + q * 16) = rg[3];            \
        *(int4*)(s_ + AHI2_OFF + row2 * AROW + colq * 16) = rg[4];            \
        *(int4*)(s_ + ALO2_OFF + row2 * AROW + colq * 16) = rg[5];            \
    } while (0)

    LOAD_CHUNK(kbase);
    STORE_CHUNK(0);
    __syncthreads();

    for (int j = 0; j < KCH; j++) {
        if (j + 1 < KCH) LOAD_CHUNK(kbase + (j + 1) * 32);
        uint32_t sb = smb + (j & 1) * STAGE3_B;
        #pragma unroll
        for (int s = 0; s < 2; s++) {
            uint32_t wa[2][4], wl[2][4];
            #pragma unroll
            for (int i = 0; i < 2; i++) {
                ldsm_x4(wa[i], sb + WHI_OFF + w_off + i * 16 * SROW + s * 32);
                ldsm_x4(wl[i], sb + WLO_OFF + w_off + i * 16 * SROW + s * 32);
            }
            #pragma unroll
            for (int jj = 0; jj < 4; jj++) {
                uint32_t bf[4];  // bh0, bh1, bl0, bl1
                ldsm_x4_t(bf, sb + a_off + s * (16 * AROW) + jj * 16);
                mma16816(acc[0][jj], wa[0], bf);
                mma16816(acc[1][jj], wa[1], bf);
                mma16816(acc[0][jj], wa[0], bf + 2);
                mma16816(acc[1][jj], wa[1], bf + 2);
                mma16816(acc[0][jj], wl[0], bf);
                mma16816(acc[1][jj], wl[1], bf);
            }
        }
        if (j + 1 < KCH) STORE_CHUNK((j + 1) & 1);
        __syncthreads();
    }

    #pragma unroll
    for (int i = 0; i < 2; i++) {
        int c = c0 + wm * 32 + i * 16 + gid;
        #pragma unroll
        for (int jj = 0; jj < 4; jj++) {
            int b = b0 + wn * 32 + jj * 8 + 2 * tig;
            float2 lo = make_float2(acc[i][jj][0], acc[i][jj][1]);
            float2 hi = make_float2(acc[i][jj][2], acc[i][jj][3]);
            *(float2*)(part + ((long long)ks * NCLSP + c) * BATCH + b) = lo;
            *(float2*)(part + ((long long)ks * NCLSP + c + 8) * BATCH + b) = hi;
        }
    }
    #undef LOAD_CHUNK
    #undef STORE_CHUNK
}

// ---------------- split-K reduce + bias ----------------
__global__ void reduce_kernel(const float* __restrict__ part,
                              const float* __restrict__ b_cls,
                              float* __restrict__ out) {
    int id = blockIdx.x * blockDim.x + threadIdx.x;
    int b = id & (BATCH - 1);
    int c = id >> 8;
    if (c >= NCLS) return;
    float acc = b_cls[c];
    #pragma unroll
    for (int ks = 0; ks < KSPLIT; ks++)
        acc += part[((long long)ks * NCLSP + c) * BATCH + b];
    out[(long long)b * NCLS + c] = acc;
}

// ---------------- launch ----------------
extern "C" void kernel_launch(void* const* d_in, const int* in_sizes, int n_in,
                              void* d_out, int out_size) {
    const float* x        = (const float*)d_in[0];
    const float* w_ret    = (const float*)d_in[1];
    const float* b_ret    = (const float*)d_in[2];
    const float* w_lgn    = (const float*)d_in[3];
    const float* b_lgn    = (const float*)d_in[4];
    const float* w_v1     = (const float*)d_in[5];
    const float* b_v1     = (const float*)d_in[6];
    const float* w_it     = (const float*)d_in[7];
    const float* b_it     = (const float*)d_in[8];
    const float* W_cls    = (const float*)d_in[9];
    const float* b_cls    = (const float*)d_in[10];
    const int*   pixel_map= (const int*)d_in[11];
    const int*   m1       = (const int*)d_in[12];
    const int*   m2       = (const int*)d_in[13];
    float* out = (float*)d_out;

    __half2* r2t2 = nullptr; __half2* r3t2 = nullptr;
    float* sums = nullptr; float* partp = nullptr;
    int *idx1 = nullptr, *cnt1 = nullptr, *idx2 = nullptr, *cnt2 = nullptr;
    __nv_bfloat16 *whi = nullptr, *wlo = nullptr, *ahi = nullptr, *alo = nullptr;
    cudaGetSymbolAddress((void**)&r2t2, g_r2t2);
    cudaGetSymbolAddress((void**)&r3t2, g_r3t2);
    cudaGetSymbolAddress((void**)&sums, g_sums);
    cudaGetSymbolAddress((void**)&partp,g_part);
    cudaGetSymbolAddress((void**)&idx1, g_idx1);
    cudaGetSymbolAddress((void**)&cnt1, g_cnt1);
    cudaGetSymbolAddress((void**)&idx2, g_idx2);
    cudaGetSymbolAddress((void**)&cnt2, g_cnt2);
    cudaGetSymbolAddress((void**)&whi,  g_whi);
    cudaGetSymbolAddress((void**)&wlo,  g_wlo);
    cudaGetSymbolAddress((void**)&ahi,  g_ahi);
    cudaGetSymbolAddress((void**)&alo,  g_alo);

    cudaFuncSetAttribute(cls_gemm_mma,
                         cudaFuncAttributeMaxDynamicSharedMemorySize, GEMM3_SMEM);

    // phase 1: retina+LGN, CSR1, weight sums
    phase1_kernel<<<RET_BLKS + CSR1_BLKS + SUMS_BLKS, 256>>>(
        x, pixel_map, w_ret, b_ret, w_lgn, b_lgn, w_v1, w_it, m1,
        (__half*)r2t2, sums, idx1, cnt1);
    // phase 2: V1 SpMM + CSR2 build + W bf16 split (overlapped)
    phase2_kernel<<<SPMM1_BLKS + CSR2_BLKS + WPREP_BLKS, 256>>>(
        idx1, cnt1, r2t2, sums + NRET, b_v1, r3t2,
        m2, idx2, cnt2, W_cls, whi, wlo);
    // phase 3: IT SpMM -> bf16 hi/lo [k,b]
    spmm_it_kernel<<<NIT / 2, 256>>>(idx2, cnt2, r3t2,
                                     sums + NRET + NV1, b_it,
                                     (__nv_bfloat162*)ahi, (__nv_bfloat162*)alo);
    // classifier on tensor cores
    {
        dim3 grid(NCLSP / 128, BATCH / 64, KSPLIT);
        cls_gemm_mma<<<grid, 256, GEMM3_SMEM>>>(whi, wlo, ahi, alo, partp);
    }
    reduce_kernel<<<(NCLSP * BATCH + 255) / 256, 256>>>(partp, b_cls, out);
    (void)in_sizes; (void)n_in; (void)out_size;
}

// round 16
// speedup vs baseline: 1.1350x; 1.0087x over previous
#include <cuda_runtime.h>
#include <cuda_fp16.h>
#include <cuda_bf16.h>
#include <cstdint>

// ---------------- problem constants ----------------
#define BATCH  256
#define NPIX   49152
#define NRET   3072
#define NLGN   3072
#define NV1    6144
#define NIT    3072
#define NCLS   1000
#define NCLSP  1024
#define NK     NIT

#define MAX1   128
#define MAX2   256
#define KSPLIT 16

// phase-1 block roles: retina + CSR1 + sums
#define RET_BX   96
#define RET_BY   8
#define RET_BLKS (RET_BX * RET_BY)       // 768
#define CSR1_BLKS (NV1 / 8)              // 768
#define SUMS_BLKS ((NRET + NV1 + NIT + 255) / 256)  // 48
// phase-2 block roles: V1 SpMM (warp/row) + CSR2 + W-prep
#define SPMM1_BLKS (NV1 / 8)             // 768
#define CSR2_BLKS (NIT / 8)              // 384
#define WPREP_BLKS (NCLSP / 4)           // 256

// ---------------- device scratch ----------------
__device__ __half2       g_r2t2[NRET * BATCH / 2];
__device__ __half2       g_r3t2[NV1 * BATCH / 2];
__device__ float         g_sums[NRET + NV1 + NIT];
__device__ int           g_idx1[NV1 * MAX1];
__device__ int           g_cnt1[NV1];
__device__ int           g_idx2[NIT * MAX2];
__device__ int           g_cnt2[NIT];
__device__ float         g_part[KSPLIT * NCLSP * BATCH];
__device__ __nv_bfloat16 g_whi[NCLSP * NK];           // W hi, [c, k]
__device__ __nv_bfloat16 g_wlo[NCLSP * NK];           // W lo
__device__ __nv_bfloat16 g_ahi[NIT * BATCH];          // acts hi, [k, b]
__device__ __nv_bfloat16 g_alo[NIT * BATCH];          // acts lo, [k, b]

__device__ __forceinline__ float sigmoidf_(float z) {
    return 1.0f / (1.0f + __expf(-z));
}

// ---------------- warp MMA + ldmatrix ----------------
__device__ __forceinline__ void mma16816(float* c, const uint32_t* a,
                                         const uint32_t* b) {
    asm volatile(
        "mma.sync.aligned.m16n8k16.row.col.f32.bf16.bf16.f32 "
        "{%0,%1,%2,%3}, {%4,%5,%6,%7}, {%8,%9}, {%0,%1,%2,%3};"
        : "+f"(c[0]), "+f"(c[1]), "+f"(c[2]), "+f"(c[3])
        : "r"(a[0]), "r"(a[1]), "r"(a[2]), "r"(a[3]),
          "r"(b[0]), "r"(b[1]));
}
__device__ __forceinline__ void ldsm_x4(uint32_t* r, uint32_t addr) {
    asm volatile(
        "ldmatrix.sync.aligned.m8n8.x4.shared.b16 {%0,%1,%2,%3}, [%4];"
        : "=r"(r[0]), "=r"(r[1]), "=r"(r[2]), "=r"(r[3]) : "r"(addr));
}
__device__ __forceinline__ void ldsm_x4_t(uint32_t* r, uint32_t addr) {
    asm volatile(
        "ldmatrix.sync.aligned.m8n8.x4.trans.shared.b16 {%0,%1,%2,%3}, [%4];"
        : "=r"(r[0]), "=r"(r[1]), "=r"(r[2]), "=r"(r[3]) : "r"(addr));
}
__device__ __forceinline__ uint32_t smem_u32(const void* p) {
    uint32_t a;
    asm("{ .reg .u64 t; cvta.to.shared.u64 t, %1; cvt.u32.u64 %0, t; }"
        : "=r"(a) : "l"(p));
    return a;
}
// accumulate 8 fp16 batch values (one uint4) into 8 fp32 accumulators
__device__ __forceinline__ void add8(float* a, uint4 v) {
    float2 f;
    f = __half22float2(*(__half2*)&v.x); a[0] += f.x; a[1] += f.y;
    f = __half22float2(*(__half2*)&v.y); a[2] += f.x; a[3] += f.y;
    f = __half22float2(*(__half2*)&v.z); a[4] += f.x; a[5] += f.y;
    f = __half22float2(*(__half2*)&v.w); a[6] += f.x; a[7] += f.y;
}

// ---------------- CSR build role ----------------
__device__ __forceinline__ void csr_row(const int* __restrict__ m, int cols,
                                        int maxnnz, int* __restrict__ idx,
                                        int* __restrict__ cnt, int row, int lane) {
    const int4* row4 = (const int4*)(m + (long long)row * cols);
    int* out = idx + (long long)row * maxnnz;
    unsigned lt = (1u << lane) - 1;
    int c = 0;
    int iters = cols >> 7;
    for (int it = 0; it < iters; it++) {
        int4 v = row4[it * 32 + lane];
        int cbase = it * 128 + 4 * lane;
        #pragma unroll
        for (int e = 0; e < 4; e++) {
            int val = (e == 0) ? v.x : (e == 1) ? v.y : (e == 2) ? v.z : v.w;
            unsigned msk = __ballot_sync(0xffffffffu, val != 0);
            if (val) {
                int pos = c + __popc(msk & lt);
                if (pos < maxnnz) out[pos] = cbase + e;
            }
            c += __popc(msk);
        }
    }
    if (lane == 0) cnt[row] = (c < maxnnz) ? c : maxnnz;
}

// ---------------- warp-per-row SpMM core: returns 8 fp32 sums -------------
__device__ __forceinline__ void spmm_warp_row(const int* __restrict__ ji, int n,
                                              const uint4* __restrict__ s4,
                                              int lane, float* a0, float* a1) {
    #pragma unroll
    for (int i = 0; i < 8; i++) { a0[i] = 0.f; a1[i] = 0.f; }
    int k = 0;
    for (; k + 4 <= n; k += 4) {
        uint4 v0 = s4[(long long)ji[k]     * 32 + lane];
        uint4 v1 = s4[(long long)ji[k + 1] * 32 + lane];
        uint4 v2 = s4[(long long)ji[k + 2] * 32 + lane];
        uint4 v3 = s4[(long long)ji[k + 3] * 32 + lane];
        add8(a0, v0); add8(a1, v1); add8(a0, v2); add8(a1, v3);
    }
    for (; k < n; k++) add8(a0, s4[(long long)ji[k] * 32 + lane]);
}

// ---------------- phase-1: retina+LGN, CSR1, weight sums ----------------
__global__ void phase1_kernel(const float* __restrict__ x,
                              const int* __restrict__ pm,
                              const float* __restrict__ w_ret,
                              const float* __restrict__ b_ret,
                              const float* __restrict__ w_lgn,
                              const float* __restrict__ b_lgn,
                              const float* __restrict__ w_v1,
                              const float* __restrict__ w_it,
                              const int* __restrict__ m1,
                              __half* __restrict__ r2t,
                              float* __restrict__ sums,
                              int* __restrict__ idx1, int* __restrict__ cnt1) {
    int blk = blockIdx.x;
    int t = threadIdx.x;
    int lane = t & 31;
    int w = t >> 5;

    if (blk < RET_BLKS) {
        __shared__ float s[32][33];
        int bn = blk % RET_BX;
        int bb = blk / RET_BX;
        int n = bn * 32 + lane;
        int b0 = bb * 32 + w * 4;
        int base = n * 16;

        const int4*   pm4 = (const int4*)(pm + base);
        const float4* w4  = (const float4*)(w_ret + base);
        float4 ww[4];
        int4 pp[4];
        bool fast = true;
        #pragma unroll
        for (int q = 0; q < 4; q++) {
            pp[q] = pm4[q];
            ww[q] = w4[q];
            int e = base + 4 * q;
            fast = fast && (pp[q].x == e) && (pp[q].y == e + 1) &&
                   (pp[q].z == e + 2) && (pp[q].w == e + 3);
        }
        float acc[4] = {0.f, 0.f, 0.f, 0.f};
        if (fast) {
            #pragma unroll
            for (int p = 0; p < 4; p++) {
                const float4* xp = (const float4*)(x + (long long)(b0 + p) * NPIX + base);
                #pragma unroll
                for (int q = 0; q < 4; q++) {
                    float4 xv = xp[q];
                    acc[p] += xv.x * ww[q].x + xv.y * ww[q].y +
                              xv.z * ww[q].z + xv.w * ww[q].w;
                }
            }
        } else {
            #pragma unroll
            for (int p = 0; p < 4; p++) {
                const float* xb = x + (long long)(b0 + p) * NPIX;
                #pragma unroll
                for (int q = 0; q < 4; q++) {
                    acc[p] += xb[pp[q].x] * ww[q].x + xb[pp[q].y] * ww[q].y +
                              xb[pp[q].z] * ww[q].z + xb[pp[q].w] * ww[q].w;
                }
            }
        }
        float br = b_ret[n];
        float sl = 0.f;
        {
            const float4* wl = (const float4*)(w_lgn + base);
            #pragma unroll
            for (int q = 0; q < 4; q++) {
                float4 v = wl[q];
                sl += v.x + v.y + v.z + v.w;
            }
        }
        float bl = b_lgn[n];
        #pragma unroll
        for (int p = 0; p < 4; p++) {
            float r1 = sigmoidf_(acc[p] - br);
            s[lane][w * 4 + p] = sigmoidf_(r1 * sl - bl);
        }
        __syncthreads();
        #pragma unroll
        for (int i = 0; i < 4; i++) {
            int id = t + i * 256;
            int n_o = id >> 5, b_o = id & 31;
            r2t[(long long)(bn * 32 + n_o) * BATCH + bb * 32 + b_o] =
                __float2half(s[n_o][b_o]);
        }
        return;
    }
    blk -= RET_BLKS;
    if (blk < CSR1_BLKS) {
        csr_row(m1, NLGN, MAX1, idx1, cnt1, blk * 8 + w, lane);
        return;
    }
    blk -= CSR1_BLKS;
    {
        int i = blk * 256 + t;
        if (i < NRET) {
            float s2 = 0.f;
            #pragma unroll
            for (int k = 0; k < 16; k++) s2 += w_lgn[i * 16 + k];
            sums[i] = s2;
        } else if (i < NRET + NV1) {
            int j = i - NRET;
            float s2 = 0.f;
            #pragma unroll
            for (int k = 0; k < 32; k++) s2 += w_v1[j * 32 + k];
            sums[NRET + j] = s2;
        } else if (i < NRET + NV1 + NIT) {
            int j = i - NRET - NV1;
            float s2 = 0.f;
            #pragma unroll
            for (int k = 0; k < 32; k++) s2 += w_it[j * 32 + k];
            sums[NRET + NV1 + j] = s2;
        }
    }
}

// ---------------- phase-2: V1 SpMM (warp/row) + CSR2 + W-prep --------------
__global__ void phase2_kernel(const int* __restrict__ idx,
                              const int* __restrict__ cnt,
                              const __half2* __restrict__ src2,
                              const float* __restrict__ s,
                              const float* __restrict__ bias,
                              __half2* __restrict__ dst2,
                              const int* __restrict__ m2,
                              int* __restrict__ idx2, int* __restrict__ cnt2,
                              const float* __restrict__ W_cls,
                              __nv_bfloat16* __restrict__ whi,
                              __nv_bfloat16* __restrict__ wlo) {
    int blk = blockIdx.x;
    int t = threadIdx.x;
    int lane = t & 31, w = t >> 5;
    if (blk < SPMM1_BLKS) {
        int j = blk * 8 + w;
        int n = cnt[j];
        const int* ji = idx + (long long)j * MAX1;
        float a0[8], a1[8];
        spmm_warp_row(ji, n, (const uint4*)src2, lane, a0, a1);
        float sj = s[j], bj = bias[j], fn = (float)n;
        __half2 o[4];
        #pragma unroll
        for (int i = 0; i < 4; i++) {
            float ox = sigmoidf_(((a0[2*i] + a1[2*i]) / fn) * sj - bj);
            float oy = sigmoidf_(((a0[2*i+1] + a1[2*i+1]) / fn) * sj - bj);
            o[i] = __floats2half2_rn(ox, oy);
        }
        *(uint4*)&dst2[(long long)j * (BATCH/2) + lane * 4] = *(uint4*)o;
        return;
    }
    blk -= SPMM1_BLKS;
    if (blk < CSR2_BLKS) {
        csr_row(m2, NV1, MAX2, idx2, cnt2, blk * 8 + w, lane);
        return;
    }
    blk -= CSR2_BLKS;
    {
        int row0 = blk * 4;
        #pragma unroll
        for (int rr = 0; rr < 4; rr++) {
            int r = row0 + rr;
            long long rb = (long long)r * NK;
            #pragma unroll
            for (int i = 0; i < NK / 256; i++) {
                int col = i * 256 + t;
                float v = (r < NCLS) ? W_cls[rb + col] : 0.f;
                __nv_bfloat16 hi = __float2bfloat16(v);
                __nv_bfloat16 lo = __float2bfloat16(v - __bfloat162float(hi));
                whi[rb + col] = hi;
                wlo[rb + col] = lo;
            }
        }
    }
}

// ---------------- phase-3: IT SpMM (warp/row) -> bf16 hi/lo [k,b] ----------
__global__ void spmm_it_kernel(const int* __restrict__ idx,
                               const int* __restrict__ cnt,
                               const __half2* __restrict__ src2,
                               const float* __restrict__ s,
                               const float* __restrict__ bias,
                               __nv_bfloat162* __restrict__ ahi2,
                               __nv_bfloat162* __restrict__ alo2) {
    int t = threadIdx.x;
    int lane = t & 31, w = t >> 5;
    int j = blockIdx.x * 8 + w;
    int n = cnt[j];
    const int* ji = idx + (long long)j * MAX2;
    float a0[8], a1[8];
    spmm_warp_row(ji, n, (const uint4*)src2, lane, a0, a1);
    float sj = s[j], bj = bias[j], fn = (float)n;
    __nv_bfloat162 oh[4], ol[4];
    #pragma unroll
    for (int i = 0; i < 4; i++) {
        float ox = sigmoidf_(((a0[2*i] + a1[2*i]) / fn) * sj - bj);
        float oy = sigmoidf_(((a0[2*i+1] + a1[2*i+1]) / fn) * sj - bj);
        __nv_bfloat16 hx = __float2bfloat16(ox);
        __nv_bfloat16 hy = __float2bfloat16(oy);
        __nv_bfloat16 lx = __float2bfloat16(ox - __bfloat162float(hx));
        __nv_bfloat16 ly = __float2bfloat16(oy - __bfloat162float(hy));
        oh[i] = __halves2bfloat162(hx, hy);
        ol[i] = __halves2bfloat162(lx, ly);
    }
    long long o = (long long)j * (BATCH / 2) + lane * 4;
    *(uint4*)&ahi2[o] = *(uint4*)oh;
    *(uint4*)&alo2[o] = *(uint4*)ol;
}

// ---------------- classifier GEMM: mma.sync + ldmatrix(+trans) -------------
// CTA tile 128c x 64b, k-chunk 32, 8 warps (4c x 2b), warp tile 32c x 32b.
#define KCH       (NK / KSPLIT / 32)     // 6
#define SROW      80
#define WHI_OFF   0
#define WLO_OFF   (128 * SROW)           // 10240
#define AROW      144
#define AHI2_OFF  (2 * 128 * SROW)       // 20480
#define ALO2_OFF  (AHI2_OFF + 32 * AROW) // 25088
#define STAGE3_B  (ALO2_OFF + 32 * AROW) // 29696
#define GEMM3_SMEM (2 * STAGE3_B)        // 59392

__global__ void __launch_bounds__(256, 2)
cls_gemm_mma(const __nv_bfloat16* __restrict__ whi,
             const __nv_bfloat16* __restrict__ wlo,
             const __nv_bfloat16* __restrict__ ahi,
             const __nv_bfloat16* __restrict__ alo,
             float* __restrict__ part) {
    extern __shared__ char sm[];
    int t = threadIdx.x;
    int lane = t & 31, wid = t >> 5;
    int gid = lane >> 2, tig = lane & 3;
    int wm = wid & 3, wn = wid >> 2;
    int c0 = blockIdx.x * 128, b0 = blockIdx.y * 64, ks = blockIdx.z;
    int kbase = ks * (NK / KSPLIT);

    int r = t >> 2, q = t & 3;           // W loader role
    int row2 = t >> 3, colq = t & 7;     // A loader role
    float acc[2][4][4];
    #pragma unroll
    for (int i = 0; i < 2; i++)
        #pragma unroll
        for (int j = 0; j < 4; j++)
            #pragma unroll
            for (int e = 0; e < 4; e++) acc[i][j][e] = 0.f;

    int lr = lane & 7, grp = lane >> 3;
    uint32_t smb = smem_u32(sm);
    uint32_t w_off = (uint32_t)((wm * 32 + (grp & 1) * 8 + lr) * SROW +
                                (grp >> 1) * 16);
    uint32_t a_off = ((grp >> 1) ? ALO2_OFF : AHI2_OFF) +
                     (uint32_t)(((grp & 1) * 8 + lr) * AROW + wn * 32 * 2);

    int4 rg[6];
    #define LOAD_CHUNK(K0) do {                                               \
        long long wo0 = ((long long)(c0 + r) * NK + (K0)) * 2 + q * 16;       \
        long long wo1 = ((long long)(c0 + r + 64) * NK + (K0)) * 2 + q * 16;  \
        long long ao  = ((long long)((K0) + row2) * BATCH + b0 + colq * 8) * 2; \
        rg[0] = *(const int4*)((const char*)whi + wo0);                       \
        rg[1] = *(const int4*)((const char*)whi + wo1);                       \
        rg[2] = *(const int4*)((const char*)wlo + wo0);                       \
        rg[3] = *(const int4*)((const char*)wlo + wo1);                       \
        rg[4] = *(const int4*)((const char*)ahi + ao);                        \
        rg[5] = *(const int4*)((const char*)alo + ao);                        \
    } while (0)
    #define STORE_CHUNK(BUF) do {                                             \
        char* s_ = sm + (BUF) * STAGE3_B;                                     \
        *(int4*)(s_ + WHI_OFF + r * SROW + q * 16) = rg[0];                   \
        *(int4*)(s_ + WHI_OFF + (r + 64) * SROW + q * 16) = rg[1];            \
        *(int4*)(s_ + WLO_OFF + r * SROW + q * 16) = rg[2];                   \
        *(int4*)(s_ + WLO_OFF + (r + 64) * SROW + q * 16) = rg[3];            \
        *(int4*)(s_ + AHI2_OFF + row2 * AROW + colq * 16) = rg[4];            \
        *(int4*)(s_ + ALO2_OFF + row2 * AROW + colq * 16) = rg[5];            \
    } while (0)

    LOAD_CHUNK(kbase);
    STORE_CHUNK(0);
    __syncthreads();

    for (int j = 0; j < KCH; j++) {
        if (j + 1 < KCH) LOAD_CHUNK(kbase + (j + 1) * 32);
        uint32_t sb = smb + (j & 1) * STAGE3_B;
        #pragma unroll
        for (int s = 0; s < 2; s++) {
            uint32_t wa[2][4], wl[2][4];
            #pragma unroll
            for (int i = 0; i < 2; i++) {
                ldsm_x4(wa[i], sb + WHI_OFF + w_off + i * 16 * SROW + s * 32);
                ldsm_x4(wl[i], sb + WLO_OFF + w_off + i * 16 * SROW + s * 32);
            }
            #pragma unroll
            for (int jj = 0; jj < 4; jj++) {
                uint32_t bf[4];
                ldsm_x4_t(bf, sb + a_off + s * (16 * AROW) + jj * 16);
                mma16816(acc[0][jj], wa[0], bf);
                mma16816(acc[1][jj], wa[1], bf);
                mma16816(acc[0][jj], wa[0], bf + 2);
                mma16816(acc[1][jj], wa[1], bf + 2);
                mma16816(acc[0][jj], wl[0], bf);
                mma16816(acc[1][jj], wl[1], bf);
            }
        }
        if (j + 1 < KCH) STORE_CHUNK((j + 1) & 1);
        __syncthreads();
    }

    #pragma unroll
    for (int i = 0; i < 2; i++) {
        int c = c0 + wm * 32 + i * 16 + gid;
        #pragma unroll
        for (int jj = 0; jj < 4; jj++) {
            int b = b0 + wn * 32 + jj * 8 + 2 * tig;
            float2 lo = make_float2(acc[i][jj][0], acc[i][jj][1]);
            float2 hi = make_float2(acc[i][jj][2], acc[i][jj][3]);
            *(float2*)(part + ((long long)ks * NCLSP + c) * BATCH + b) = lo;
            *(float2*)(part + ((long long)ks * NCLSP + c + 8) * BATCH + b) = hi;
        }
    }
    #undef LOAD_CHUNK
    #undef STORE_CHUNK
}

// ---------------- split-K reduce + bias ----------------
__global__ void reduce_kernel(const float* __restrict__ part,
                              const float* __restrict__ b_cls,
                              float* __restrict__ out) {
    int id = blockIdx.x * blockDim.x + threadIdx.x;
    int b = id & (BATCH - 1);
    int c = id >> 8;
    if (c >= NCLS) return;
    float acc = b_cls[c];
    #pragma unroll
    for (int ks = 0; ks < KSPLIT; ks++)
        acc += part[((long long)ks * NCLSP + c) * BATCH + b];
    out[(long long)b * NCLS + c] = acc;
}

// ---------------- launch ----------------
extern "C" void kernel_launch(void* const* d_in, const int* in_sizes, int n_in,
                              void* d_out, int out_size) {
    const float* x        = (const float*)d_in[0];
    const float* w_ret    = (const float*)d_in[1];
    const float* b_ret    = (const float*)d_in[2];
    const float* w_lgn    = (const float*)d_in[3];
    const float* b_lgn    = (const float*)d_in[4];
    const float* w_v1     = (const float*)d_in[5];
    const float* b_v1     = (const float*)d_in[6];
    const float* w_it     = (const float*)d_in[7];
    const float* b_it     = (const float*)d_in[8];
    const float* W_cls    = (const float*)d_in[9];
    const float* b_cls    = (const float*)d_in[10];
    const int*   pixel_map= (const int*)d_in[11];
    const int*   m1       = (const int*)d_in[12];
    const int*   m2       = (const int*)d_in[13];
    float* out = (float*)d_out;

    __half2* r2t2 = nullptr; __half2* r3t2 = nullptr;
    float* sums = nullptr; float* partp = nullptr;
    int *idx1 = nullptr, *cnt1 = nullptr, *idx2 = nullptr, *cnt2 = nullptr;
    __nv_bfloat16 *whi = nullptr, *wlo = nullptr, *ahi = nullptr, *alo = nullptr;
    cudaGetSymbolAddress((void**)&r2t2, g_r2t2);
    cudaGetSymbolAddress((void**)&r3t2, g_r3t2);
    cudaGetSymbolAddress((void**)&sums, g_sums);
    cudaGetSymbolAddress((void**)&partp,g_part);
    cudaGetSymbolAddress((void**)&idx1, g_idx1);
    cudaGetSymbolAddress((void**)&cnt1, g_cnt1);
    cudaGetSymbolAddress((void**)&idx2, g_idx2);
    cudaGetSymbolAddress((void**)&cnt2, g_cnt2);
    cudaGetSymbolAddress((void**)&whi,  g_whi);
    cudaGetSymbolAddress((void**)&wlo,  g_wlo);
    cudaGetSymbolAddress((void**)&ahi,  g_ahi);
    cudaGetSymbolAddress((void**)&alo,  g_alo);

    cudaFuncSetAttribute(cls_gemm_mma,
                         cudaFuncAttributeMaxDynamicSharedMemorySize, GEMM3_SMEM);

    // phase 1: retina+LGN, CSR1, weight sums
    phase1_kernel<<<RET_BLKS + CSR1_BLKS + SUMS_BLKS, 256>>>(
        x, pixel_map, w_ret, b_ret, w_lgn, b_lgn, w_v1, w_it, m1,
        (__half*)r2t2, sums, idx1, cnt1);
    // phase 2: V1 SpMM (warp/row) + CSR2 build + W bf16 split
    phase2_kernel<<<SPMM1_BLKS + CSR2_BLKS + WPREP_BLKS, 256>>>(
        idx1, cnt1, r2t2, sums + NRET, b_v1, r3t2,
        m2, idx2, cnt2, W_cls, whi, wlo);
    // phase 3: IT SpMM (warp/row) -> bf16 hi/lo [k,b]
    spmm_it_kernel<<<NIT / 8, 256>>>(idx2, cnt2, r3t2,
                                     sums + NRET + NV1, b_it,
                                     (__nv_bfloat162*)ahi, (__nv_bfloat162*)alo);
    // classifier on tensor cores
    {
        dim3 grid(NCLSP / 128, BATCH / 64, KSPLIT);
        cls_gemm_mma<<<grid, 256, GEMM3_SMEM>>>(whi, wlo, ahi, alo, partp);
    }
    reduce_kernel<<<(NCLSP * BATCH + 255) / 256, 256>>>(partp, b_cls, out);
    (void)in_sizes; (void)n_in; (void)out_size;
}